// round 13
// baseline (speedup 1.0000x reference)
#include <cuda_runtime.h>
#include <cuda_fp16.h>
#include <math.h>
#include <stdint.h>

#define DIMC 1536
#define NHEAD 12
#define HDIM 128
#define SEQ 5400
#define GHW 900
#define GWID 30

// scratch (device globals: no allocations allowed)
__device__ float  g_qf[SEQ * DIMC];
__device__ float  g_kf[SEQ * DIMC];
__device__ __half g_qh[SEQ * DIMC];
__device__ __half g_kh[SEQ * DIMC];
__device__ __half g_vt[NHEAD * HDIM * SEQ + 256];   // [head][d][seq] (+pad)
__device__ __half g_ao[SEQ * DIMC];
__device__ __half g_xh[SEQ * DIMC];
__device__ __half g_wh[4][DIMC * DIMC];

// ---------------------------------------------------------------------------
// helpers
// ---------------------------------------------------------------------------
__device__ __forceinline__ void mma_f16(float* c, const uint32_t* a,
                                        uint32_t b0, uint32_t b1) {
    asm volatile(
        "mma.sync.aligned.m16n8k16.row.col.f32.f16.f16.f32 "
        "{%0,%1,%2,%3}, {%4,%5,%6,%7}, {%8,%9}, {%0,%1,%2,%3};\n"
        : "+f"(c[0]), "+f"(c[1]), "+f"(c[2]), "+f"(c[3])
        : "r"(a[0]), "r"(a[1]), "r"(a[2]), "r"(a[3]), "r"(b0), "r"(b1));
}

__device__ __forceinline__ void ldsm4(uint32_t& r0, uint32_t& r1,
                                      uint32_t& r2, uint32_t& r3, uint32_t a) {
    asm volatile("ldmatrix.sync.aligned.m8n8.x4.shared.b16 {%0,%1,%2,%3}, [%4];"
                 : "=r"(r0), "=r"(r1), "=r"(r2), "=r"(r3) : "r"(a));
}

__device__ __forceinline__ void sts32(uint32_t a, uint32_t v) {
    asm volatile("st.shared.b32 [%0], %1;" :: "r"(a), "r"(v) : "memory");
}

__device__ __forceinline__ void barn(int id, int cnt) {
    asm volatile("bar.sync %0, %1;" :: "r"(id), "r"(cnt) : "memory");
}

__device__ __forceinline__ void cp16(uint32_t dst, const void* src) {
    asm volatile("cp.async.cg.shared.global [%0], [%1], 16;\n"
                 :: "r"(dst), "l"(src));
}
__device__ __forceinline__ void cp_commit() {
    asm volatile("cp.async.commit_group;\n");
}
template <int N> __device__ __forceinline__ void cp_wait() {
    asm volatile("cp.async.wait_group %0;\n" :: "n"(N));
}

// exp2 on a packed pair: arg pair (fp32) -> fp16x2 -> h2exp2 -> packed P
__device__ __forceinline__ uint32_t pexp2(float a, float b, float2& fsum) {
    __half2 h = h2exp2(__floats2half2_rn(a, b));
    float2 f = __half22float2(h);
    fsum.x += f.x; fsum.y += f.y;
    return *(uint32_t*)&h;
}

// ---------------------------------------------------------------------------
// fp32 -> fp16 conversion copies
// ---------------------------------------------------------------------------
__global__ void __launch_bounds__(256) conv_h(
    const float4* __restrict__ s, __half2* __restrict__ d, int n4)
{
    int i = blockIdx.x * 256 + threadIdx.x;
    if (i < n4) {
        float4 v = s[i];
        d[2 * i + 0] = __floats2half2_rn(v.x, v.y);
        d[2 * i + 1] = __floats2half2_rn(v.z, v.w);
    }
}

__global__ void __launch_bounds__(256) conv_h4(
    const float4* __restrict__ s0, const float4* __restrict__ s1,
    const float4* __restrict__ s2, const float4* __restrict__ s3,
    __half2* __restrict__ d, int n4)
{
    const float4* s = (blockIdx.y == 0) ? s0 : (blockIdx.y == 1) ? s1
                     : (blockIdx.y == 2) ? s2 : s3;
    __half2* dd = d + (size_t)blockIdx.y * n4 * 2;
    int i = blockIdx.x * 256 + threadIdx.x;
    if (i < n4) {
        float4 v = s[i];
        dd[2 * i + 0] = __floats2half2_rn(v.x, v.y);
        dd[2 * i + 1] = __floats2half2_rn(v.z, v.w);
    }
}

// ---------------------------------------------------------------------------
// FP16 GEMM core: 128x128 tile, BK=64, 3-stage cp.async pipeline,
// ONE __syncthreads per k-block (24 total). Warp tile 64x32 (8 warps 2x4).
// ---------------------------------------------------------------------------
#define GSTRH 72                        // halves per smem row (64 + 8 pad)
#define GBUF_H (128 * GSTRH)            // halves per stage per matrix
#define GSM_BYTES (3 * GBUF_H * 2 * 2)  // 110592 bytes

struct GemmCore {
    template <typename EPI>
    static __device__ __forceinline__ void run(
        const __half* __restrict__ A, const __half* __restrict__ B,
        int bm, int bn, int M, __half* gsm, EPI epi)
    {
        __half* sA = gsm;
        __half* sB = gsm + 3 * GBUF_H;
        const int tid = threadIdx.x;
        const int lane = tid & 31;
        const int wid = tid >> 5;
        const int wm = wid & 1;
        const int wn = wid >> 1;
        const uint32_t aAddr = (uint32_t)__cvta_generic_to_shared(sA);
        const uint32_t bAddr = (uint32_t)__cvta_generic_to_shared(sB);
        const uint32_t aOff = ((wm * 64 + (lane & 15)) * GSTRH + (lane >> 4) * 8) * 2;
        const uint32_t bOff = ((wn * 32 + (lane & 7) + ((lane >> 4) & 1) * 8) * GSTRH
                               + ((lane >> 3) & 1) * 8) * 2;

        float acc[4][4][4];
#pragma unroll
        for (int mt = 0; mt < 4; ++mt)
#pragma unroll
            for (int nt = 0; nt < 4; ++nt)
#pragma unroll
                for (int i = 0; i < 4; ++i) acc[mt][nt][i] = 0.f;

        auto fill = [&](int stg, int kb) {
            const int k0 = kb * 64;
            const uint32_t ab = aAddr + stg * GBUF_H * 2;
            const uint32_t bb = bAddr + stg * GBUF_H * 2;
#pragma unroll
            for (int i = 0; i < 4; ++i) {
                int c = tid + i * 256;          // 0..1023
                int r = c >> 3, c8 = c & 7;
                int ra = bm + r; if (ra > M - 1) ra = M - 1;
                cp16(ab + (r * GSTRH + 8 * c8) * 2,
                     A + (size_t)ra * DIMC + k0 + 8 * c8);
                cp16(bb + (r * GSTRH + 8 * c8) * 2,
                     B + (size_t)(bn + r) * DIMC + k0 + 8 * c8);
            }
            cp_commit();
        };

        fill(0, 0);
        fill(1, 1);

        const int NKB = DIMC / 64;   // 24
        int stg = 0;
        for (int kb = 0; kb < NKB; ++kb) {
            cp_wait<1>();            // stage for kb complete
            __syncthreads();         // all warps past reads of stage (kb+2)%3
            if (kb + 2 < NKB) fill((kb + 2) % 3, kb + 2);

            const uint32_t ab = aAddr + stg * GBUF_H * 2 + aOff;
            const uint32_t bb = bAddr + stg * GBUF_H * 2 + bOff;
#pragma unroll
            for (int ks = 0; ks < 4; ++ks) {
                uint32_t af[4][4], bf[2][4];
#pragma unroll
                for (int mt = 0; mt < 4; ++mt)
                    ldsm4(af[mt][0], af[mt][1], af[mt][2], af[mt][3],
                          ab + (mt * 16 * GSTRH + ks * 16) * 2);
#pragma unroll
                for (int p = 0; p < 2; ++p)
                    ldsm4(bf[p][0], bf[p][1], bf[p][2], bf[p][3],
                          bb + (p * 16 * GSTRH + ks * 16) * 2);
#pragma unroll
                for (int mt = 0; mt < 4; ++mt)
#pragma unroll
                    for (int p = 0; p < 2; ++p) {
                        mma_f16(acc[mt][2 * p],     af[mt], bf[p][0], bf[p][1]);
                        mma_f16(acc[mt][2 * p + 1], af[mt], bf[p][2], bf[p][3]);
                    }
            }
            stg = (stg + 1) % 3;
        }
        epi(acc);
    }
};

__global__ void __launch_bounds__(256, 2) gemm_qkv(
    const __half* __restrict__ A, const __half* __restrict__ W,
    const float* __restrict__ qb, const float* __restrict__ kb_,
    const float* __restrict__ vb,
    float* __restrict__ Cq, float* __restrict__ Ck,
    __half* __restrict__ Vt, int M)
{
    extern __shared__ __half gsm[];
    const int z = blockIdx.z;
    const int tid = threadIdx.x;
    const int lane = tid & 31;
    const int wid = tid >> 5;
    const int gid = lane >> 2;
    const int tig = lane & 3;
    const int wm = wid & 1;
    const int wn = wid >> 1;
    const int bm = blockIdx.y * 128;
    const int bn = blockIdx.x * 128;
    const __half* B = W + (size_t)z * DIMC * DIMC;
    const float* bias = (z == 0) ? qb : (z == 1) ? kb_ : vb;
    float* Cf = (z == 0) ? Cq : Ck;

    GemmCore::run(A, B, bm, bn, M, gsm, [&](float acc[4][4][4]) {
#pragma unroll
        for (int mt = 0; mt < 4; ++mt) {
            int r0 = bm + wm * 64 + mt * 16 + gid;
            int r1 = r0 + 8;
#pragma unroll
            for (int nt = 0; nt < 4; ++nt) {
                int col = bn + wn * 32 + nt * 8 + 2 * tig;
                float b0 = __ldg(bias + col), b1 = __ldg(bias + col + 1);
                if (z < 2) {
                    if (r0 < M)
                        *(float2*)(Cf + (size_t)r0 * DIMC + col) =
                            make_float2(acc[mt][nt][0] + b0, acc[mt][nt][1] + b1);
                    if (r1 < M)
                        *(float2*)(Cf + (size_t)r1 * DIMC + col) =
                            make_float2(acc[mt][nt][2] + b0, acc[mt][nt][3] + b1);
                } else {
                    if (r0 < M) {
                        Vt[(size_t)col * SEQ + r0]       = __float2half_rn(acc[mt][nt][0] + b0);
                        Vt[(size_t)(col + 1) * SEQ + r0] = __float2half_rn(acc[mt][nt][1] + b1);
                    }
                    if (r1 < M) {
                        Vt[(size_t)col * SEQ + r1]       = __float2half_rn(acc[mt][nt][2] + b0);
                        Vt[(size_t)(col + 1) * SEQ + r1] = __float2half_rn(acc[mt][nt][3] + b1);
                    }
                }
            }
        }
    });
}

__global__ void __launch_bounds__(256, 2) gemm_o(
    const __half* __restrict__ A, const __half* __restrict__ B,
    const float* __restrict__ bias, float* __restrict__ Cf, int M)
{
    extern __shared__ __half gsm[];
    const int tid = threadIdx.x;
    const int lane = tid & 31;
    const int wid = tid >> 5;
    const int gid = lane >> 2;
    const int tig = lane & 3;
    const int wm = wid & 1;
    const int wn = wid >> 1;
    const int bm = blockIdx.y * 128;
    const int bn = blockIdx.x * 128;

    GemmCore::run(A, B, bm, bn, M, gsm, [&](float acc[4][4][4]) {
#pragma unroll
        for (int mt = 0; mt < 4; ++mt) {
            int r0 = bm + wm * 64 + mt * 16 + gid;
            int r1 = r0 + 8;
#pragma unroll
            for (int nt = 0; nt < 4; ++nt) {
                int col = bn + wn * 32 + nt * 8 + 2 * tig;
                float b0 = __ldg(bias + col), b1 = __ldg(bias + col + 1);
                if (r0 < M)
                    *(float2*)(Cf + (size_t)r0 * DIMC + col) =
                        make_float2(acc[mt][nt][0] + b0, acc[mt][nt][1] + b1);
                if (r1 < M)
                    *(float2*)(Cf + (size_t)r1 * DIMC + col) =
                        make_float2(acc[mt][nt][2] + b0, acc[mt][nt][3] + b1);
            }
        }
    });
}

// ---------------------------------------------------------------------------
// Fused RMSNorm + RoPE: reads fp32 q/k projections, writes fp16.
// q pre-scaled by log2(e)/sqrt(HD)  (QK scores come out in log2 domain).
// ---------------------------------------------------------------------------
__global__ void __launch_bounds__(256) norm_rope_kernel(
    const float* __restrict__ nqw, const float* __restrict__ nkw,
    const float* __restrict__ cosT, const float* __restrict__ sinT)
{
    __shared__ float buf[DIMC];
    __shared__ float red[8];
    const int row = blockIdx.x;
    const float* src = blockIdx.y ? g_kf : g_qf;
    __half* dst = blockIdx.y ? g_kh : g_qh;
    const float* w = blockIdx.y ? nkw : nqw;
    const float sc = blockIdx.y ? 1.0f
                   : (0.08838834764831845f * 1.4426950408889634f);
    const int tid = threadIdx.x;

    float ss = 0.f;
#pragma unroll
    for (int j = tid; j < DIMC; j += 256) {
        float v = src[(size_t)row * DIMC + j];
        buf[j] = v;
        ss += v * v;
    }
#pragma unroll
    for (int o = 16; o; o >>= 1) ss += __shfl_xor_sync(0xffffffffu, ss, o);
    if ((tid & 31) == 0) red[tid >> 5] = ss;
    __syncthreads();
    float tot = 0.f;
#pragma unroll
    for (int i = 0; i < 8; ++i) tot += red[i];
    const float rms = rsqrtf(tot * (1.0f / DIMC) + 1e-6f);
#pragma unroll
    for (int j = tid; j < DIMC; j += 256) buf[j] = buf[j] * rms * w[j];
    __syncthreads();

    const int f = row / GHW;
    const int rem = row - f * GHW;
    const int h = rem / GWID;
    const int ww = rem - h * GWID;
#pragma unroll
    for (int p = tid; p < DIMC / 2; p += 256) {
        int n = p >> 6;
        int i = p & 63;
        int pos = (i < 22) ? f : (i < 43) ? h : ww;
        float c = cosT[pos * 64 + i];
        float s = sinT[pos * 64 + i];
        int idx = n * HDIM + 2 * i;
        float xr = buf[idx], xi = buf[idx + 1];
        *(__half2*)(dst + (size_t)row * DIMC + idx) =
            __floats2half2_rn((xr * c - xi * s) * sc,
                              (xr * s + xi * c) * sc);
    }
}

// ---------------------------------------------------------------------------
// Flash attention: 4(m) x 2(n) warps, BQ=128, BK=64, 256 threads.
// K AND V double-buffered -> single __syncthreads per tile; both prefetches
// issue at tile top in one cp group. exp2-domain softmax (fp16-pair MUFU).
// smem (halves): Q 17408 | K 2x8704=17408 | V 2x9216=18432 | P 9216 | ex 1024f
// total bytes = (17408+17408+18432+9216)*2 + 2048 = 126976  (1 CTA/SM)
// ---------------------------------------------------------------------------
#define AKSTR 136
#define AVSTR 72
#define APSTR 72
#define AQ_H 0
#define AK_H 17408
#define AV_H (AK_H + 2 * 64 * AKSTR)       // 34816
#define AP_H (AV_H + 2 * 128 * AVSTR)      // 53248
#define AEX_B ((AP_H + 128 * APSTR) * 2)   // 124928
#define AEXS_B (AEX_B + 1024)
#define ATT_SMEM_BYTES (AEX_B + 2048)      // 126976

__global__ void __launch_bounds__(256, 1) attn_mma()
{
    extern __shared__ __half smh[];
    const uint32_t base = (uint32_t)__cvta_generic_to_shared(smh);
    const uint32_t Qb = base;
    const uint32_t Kb = base + AK_H * 2;
    const uint32_t Vb = base + AV_H * 2;
    const uint32_t Pb = base + AP_H * 2;
    float* exM = (float*)((char*)smh + AEX_B);
    float* exS = (float*)((char*)smh + AEXS_B);

    const int tid = threadIdx.x;
    const int lane = tid & 31;
    const int w = tid >> 5;
    const int wm = w & 3;
    const int wn = w >> 2;
    const int gid = lane >> 2;
    const int tig = lane & 3;
    const int qrow = wm * 32;
    const int q0 = blockIdx.x * 128;
    const int head = blockIdx.y;
    const int hoff = head * HDIM;

    const int aRow = lane & 15;
    const int aCol = (lane >> 4) * 8;
    const uint32_t qOff0 = ((qrow + aRow) * AKSTR + aCol) * 2;
    const uint32_t qOff1 = qOff0 + 16 * AKSTR * 2;
    const uint32_t pOff0 = ((qrow + aRow) * APSTR + aCol) * 2;
    const uint32_t pOff1 = pOff0 + 16 * APSTR * 2;
    const int bRow = (lane & 7) + ((lane >> 4) & 1) * 8;
    const int bCol = ((lane >> 3) & 1) * 8;
    const uint32_t kOff = ((wn * 32 + bRow) * AKSTR + bCol) * 2;
    const uint32_t vOff = ((wn * 64 + bRow) * AVSTR + bCol) * 2;

    // ---- initial fills: Q (persistent), K(0), V(0) ----
#pragma unroll
    for (int i = 0; i < 8; ++i) {
        int c = tid + i * 256;
        int r = c >> 4, c16 = c & 15;
        int sr = q0 + r; if (sr > SEQ - 1) sr = SEQ - 1;
        cp16(Qb + (r * AKSTR + 8 * c16) * 2,
             g_qh + (size_t)sr * DIMC + hoff + 8 * c16);
    }
    auto fillK = [&](int buf, int k0) {
#pragma unroll
        for (int i = 0; i < 4; ++i) {
            int c = tid + i * 256;
            int r = c >> 4, c16 = c & 15;
            int sr = k0 + r; if (sr > SEQ - 1) sr = SEQ - 1;
            cp16(Kb + ((buf * 64 + r) * AKSTR + 8 * c16) * 2,
                 g_kh + (size_t)sr * DIMC + hoff + 8 * c16);
        }
    };
    auto fillV = [&](int buf, int k0) {
#pragma unroll
        for (int i = 0; i < 4; ++i) {
            int c = tid + i * 256;
            int r = c >> 3, c8 = c & 7;
            cp16(Vb + (buf * 128 * AVSTR + r * AVSTR + 8 * c8) * 2,
                 g_vt + (size_t)(hoff + r) * SEQ + k0 + 8 * c8);
        }
    };
    fillK(0, 0);
    fillV(0, 0);
    cp_commit();

    float oacc[2][8][4];
#pragma unroll
    for (int mq = 0; mq < 2; ++mq)
#pragma unroll
        for (int dt = 0; dt < 8; ++dt)
#pragma unroll
            for (int i = 0; i < 4; ++i) oacc[mq][dt][i] = 0.f;
    float m[2][2] = {{-1e30f, -1e30f}, {-1e30f, -1e30f}};
    float l[2][2] = {{0.f, 0.f}, {0.f, 0.f}};

    const int nkt = (SEQ + 63) / 64;   // 85
    for (int kt = 0; kt < nkt; ++kt) {
        const int buf = kt & 1;
        const int k0 = kt * 64;
        cp_wait<0>();
        __syncthreads();      // single per-tile barrier: orders K/V/P/ex reuse

        // ---- prefetch K(t+1) + V(t+1) into buf^1 (free since tile t-1) ----
        if (kt + 1 < nkt) {
            fillK(buf ^ 1, k0 + 64);
            fillV(buf ^ 1, k0 + 64);
            cp_commit();
        }

        // ---- S = Q K^T (scores in log2 domain; Q pre-scaled) ----
        float sacc[2][4][4];
#pragma unroll
        for (int mq = 0; mq < 2; ++mq)
#pragma unroll
            for (int nt = 0; nt < 4; ++nt)
#pragma unroll
                for (int i = 0; i < 4; ++i) sacc[mq][nt][i] = 0.f;

        const uint32_t kbA = Kb + buf * 64 * AKSTR * 2 + kOff;
#pragma unroll
        for (int ks = 0; ks < 8; ++ks) {
            uint32_t qa0[4], qa1[4];
            ldsm4(qa0[0], qa0[1], qa0[2], qa0[3], Qb + qOff0 + ks * 32);
            ldsm4(qa1[0], qa1[1], qa1[2], qa1[3], Qb + qOff1 + ks * 32);
#pragma unroll
            for (int p = 0; p < 2; ++p) {
                uint32_t b0, b1, b2, b3;
                ldsm4(b0, b1, b2, b3, kbA + (p * 16 * AKSTR + ks * 16) * 2);
                mma_f16(sacc[0][2 * p],     qa0, b0, b1);
                mma_f16(sacc[0][2 * p + 1], qa0, b2, b3);
                mma_f16(sacc[1][2 * p],     qa1, b0, b1);
                mma_f16(sacc[1][2 * p + 1], qa1, b2, b3);
            }
        }

        // ---- mask tail keys (warp's slice) ----
        const int krem = SEQ - k0 - wn * 32;
        if (krem < 32) {
#pragma unroll
            for (int mq = 0; mq < 2; ++mq)
#pragma unroll
                for (int nt = 0; nt < 4; ++nt) {
                    int c = nt * 8 + 2 * tig;
                    if (c >= krem)     { sacc[mq][nt][0] = -1e30f; sacc[mq][nt][2] = -1e30f; }
                    if (c + 1 >= krem) { sacc[mq][nt][1] = -1e30f; sacc[mq][nt][3] = -1e30f; }
                }
        }

        // ---- partial row max + cross-warp combine ----
        float mx[2][2] = {{-1e30f, -1e30f}, {-1e30f, -1e30f}};
#pragma unroll
        for (int mq = 0; mq < 2; ++mq)
#pragma unroll
            for (int nt = 0; nt < 4; ++nt) {
                mx[mq][0] = fmaxf(mx[mq][0], fmaxf(sacc[mq][nt][0], sacc[mq][nt][1]));
                mx[mq][1] = fmaxf(mx[mq][1], fmaxf(sacc[mq][nt][2], sacc[mq][nt][3]));
            }
#pragma unroll
        for (int mq = 0; mq < 2; ++mq)
#pragma unroll
            for (int h = 0; h < 2; ++h) {
                mx[mq][h] = fmaxf(mx[mq][h], __shfl_xor_sync(0xffffffffu, mx[mq][h], 1));
                mx[mq][h] = fmaxf(mx[mq][h], __shfl_xor_sync(0xffffffffu, mx[mq][h], 2));
            }
        if (tig == 0) {
#pragma unroll
            for (int mq = 0; mq < 2; ++mq) {
                exM[wn * 128 + qrow + mq * 16 + gid]     = mx[mq][0];
                exM[wn * 128 + qrow + mq * 16 + gid + 8] = mx[mq][1];
            }
        }
        barn(1 + wm, 64);

        float f[2][2];
#pragma unroll
        for (int mq = 0; mq < 2; ++mq)
#pragma unroll
            for (int h = 0; h < 2; ++h) {
                float oth = exM[(wn ^ 1) * 128 + qrow + mq * 16 + gid + h * 8];
                float mn = fmaxf(m[mq][h], fmaxf(mx[mq][h], oth));
                f[mq][h] = exp2f(m[mq][h] - mn);
                m[mq][h] = mn;
            }

        // ---- P = exp2(s - m) in fp16 pairs; fp32 partial sums ----
        float2 ps2[2][2] = {{{0.f,0.f},{0.f,0.f}}, {{0.f,0.f},{0.f,0.f}}};
        uint32_t ph[2][2][4];
#pragma unroll
        for (int mq = 0; mq < 2; ++mq) {
#pragma unroll
            for (int nt = 0; nt < 4; ++nt) {
                int kc = nt >> 1, o = (nt & 1) * 2;
                ph[mq][kc][o] = pexp2(sacc[mq][nt][0] - m[mq][0],
                                      sacc[mq][nt][1] - m[mq][0], ps2[mq][0]);
                ph[mq][kc][o + 1] = pexp2(sacc[mq][nt][2] - m[mq][1],
                                          sacc[mq][nt][3] - m[mq][1], ps2[mq][1]);
            }
#pragma unroll
            for (int kc = 0; kc < 2; ++kc) {
                uint32_t pr = Pb + ((qrow + mq * 16 + gid) * APSTR
                                    + wn * 32 + kc * 16 + 2 * tig) * 2;
                sts32(pr,                      ph[mq][kc][0]);
                sts32(pr + 8 * APSTR * 2,      ph[mq][kc][1]);
                sts32(pr + 16,                 ph[mq][kc][2]);
                sts32(pr + 8 * APSTR * 2 + 16, ph[mq][kc][3]);
            }
        }
        float ps[2][2];
#pragma unroll
        for (int mq = 0; mq < 2; ++mq)
#pragma unroll
            for (int h = 0; h < 2; ++h) {
                ps[mq][h] = ps2[mq][h].x + ps2[mq][h].y;
                ps[mq][h] += __shfl_xor_sync(0xffffffffu, ps[mq][h], 1);
                ps[mq][h] += __shfl_xor_sync(0xffffffffu, ps[mq][h], 2);
            }
        if (tig == 0) {
#pragma unroll
            for (int mq = 0; mq < 2; ++mq) {
                exS[wn * 128 + qrow + mq * 16 + gid]     = ps[mq][0];
                exS[wn * 128 + qrow + mq * 16 + gid + 8] = ps[mq][1];
            }
        }
        barn(1 + wm, 64);

#pragma unroll
        for (int mq = 0; mq < 2; ++mq)
#pragma unroll
            for (int h = 0; h < 2; ++h) {
                float oth = exS[(wn ^ 1) * 128 + qrow + mq * 16 + gid + h * 8];
                l[mq][h] = l[mq][h] * f[mq][h] + ps[mq][h] + oth;
            }
#pragma unroll
        for (int mq = 0; mq < 2; ++mq)
#pragma unroll
            for (int dt = 0; dt < 8; ++dt) {
                oacc[mq][dt][0] *= f[mq][0]; oacc[mq][dt][1] *= f[mq][0];
                oacc[mq][dt][2] *= f[mq][1]; oacc[mq][dt][3] *= f[mq][1];
            }

        // ---- O += P V (32 rows x 64 d per warp, all 64 keys) ----
        const uint32_t vbA = Vb + buf * 128 * AVSTR * 2 + vOff;
#pragma unroll
        for (int kc = 0; kc < 4; ++kc) {
            uint32_t pa0[4], pa1[4];
            if ((kc >> 1) == wn) {
#pragma unroll
                for (int i = 0; i < 4; ++i) {
                    pa0[i] = ph[0][kc & 1][i];
                    pa1[i] = ph[1][kc & 1][i];
                }
            } else {
                ldsm4(pa0[0], pa0[1], pa0[2], pa0[3], Pb + pOff0 + kc * 32);
                ldsm4(pa1[0], pa1[1], pa1[2], pa1[3], Pb + pOff1 + kc * 32);
            }
#pragma unroll
            for (int p = 0; p < 4; ++p) {
                uint32_t v0, v1, v2, v3;
                ldsm4(v0, v1, v2, v3, vbA + (p * 16 * AVSTR + kc * 16) * 2);
                mma_f16(oacc[0][2 * p],     pa0, v0, v1);
                mma_f16(oacc[0][2 * p + 1], pa0, v2, v3);
                mma_f16(oacc[1][2 * p],     pa1, v0, v1);
                mma_f16(oacc[1][2 * p + 1], pa1, v2, v3);
            }
        }
        // no bottom sync: next tile's top __syncthreads orders all reuse
    }

    // ---- epilogue ----
#pragma unroll
    for (int mq = 0; mq < 2; ++mq) {
        float inv0 = 1.f / l[mq][0], inv1 = 1.f / l[mq][1];
        int r0 = q0 + qrow + mq * 16 + gid;
        int r1 = r0 + 8;
#pragma unroll
        for (int dt = 0; dt < 8; ++dt) {
            int col = hoff + wn * 64 + dt * 8 + 2 * tig;
            if (r0 < SEQ)
                *(__half2*)(g_ao + (size_t)r0 * DIMC + col) =
                    __floats2half2_rn(oacc[mq][dt][0] * inv0, oacc[mq][dt][1] * inv0);
            if (r1 < SEQ)
                *(__half2*)(g_ao + (size_t)r1 * DIMC + col) =
                    __floats2half2_rn(oacc[mq][dt][2] * inv1, oacc[mq][dt][3] * inv1);
        }
    }
}

// ---------------------------------------------------------------------------
extern "C" void kernel_launch(void* const* d_in, const int* in_sizes, int n_in,
                              void* d_out, int out_size)
{
    const float* x    = (const float*)d_in[0];
    const float* q_b  = (const float*)d_in[2];
    const float* k_b  = (const float*)d_in[4];
    const float* v_b  = (const float*)d_in[6];
    const float* o_b  = (const float*)d_in[8];
    const float* nqw  = (const float*)d_in[9];
    const float* nkw  = (const float*)d_in[10];
    const float* cosT = (const float*)d_in[11];
    const float* sinT = (const float*)d_in[12];
    float* out = (float*)d_out;

    float *dqf, *dkf;
    __half *dvt, *dxh, *dwh, *dao;
    cudaGetSymbolAddress((void**)&dqf, g_qf);
    cudaGetSymbolAddress((void**)&dkf, g_kf);
    cudaGetSymbolAddress((void**)&dvt, g_vt);
    cudaGetSymbolAddress((void**)&dxh, g_xh);
    cudaGetSymbolAddress((void**)&dwh, g_wh);
    cudaGetSymbolAddress((void**)&dao, g_ao);

    // convert inputs to fp16
    const int nx4 = SEQ * DIMC / 4;
    const int nw4 = DIMC * DIMC / 4;
    conv_h<<<(nx4 + 255) / 256, 256>>>((const float4*)x, (__half2*)dxh, nx4);
    conv_h4<<<dim3((nw4 + 255) / 256, 4), 256>>>(
        (const float4*)d_in[1], (const float4*)d_in[3],
        (const float4*)d_in[5], (const float4*)d_in[7],
        (__half2*)dwh, nw4);

    cudaFuncSetAttribute(gemm_qkv,
                         cudaFuncAttributeMaxDynamicSharedMemorySize, GSM_BYTES);
    cudaFuncSetAttribute(gemm_o,
                         cudaFuncAttributeMaxDynamicSharedMemorySize, GSM_BYTES);

    dim3 gQKV(DIMC / 128, (SEQ + 127) / 128, 3);
    gemm_qkv<<<gQKV, 256, GSM_BYTES>>>(dxh, dwh, q_b, k_b, v_b,
                                       dqf, dkf, dvt, SEQ);

    norm_rope_kernel<<<dim3(SEQ, 2), 256>>>(nqw, nkw, cosT, sinT);

    cudaFuncSetAttribute(attn_mma,
                         cudaFuncAttributeMaxDynamicSharedMemorySize, ATT_SMEM_BYTES);
    attn_mma<<<dim3((SEQ + 127) / 128, NHEAD), 256, ATT_SMEM_BYTES>>>();

    dim3 gGemm(DIMC / 128, (SEQ + 127) / 128);
    gemm_o<<<gGemm, 256, GSM_BYTES>>>(dao, dwh + 3 * (size_t)DIMC * DIMC,
                                      o_b, out, SEQ);
}

// round 15
// speedup vs baseline: 1.0732x; 1.0732x over previous
#include <cuda_runtime.h>
#include <cuda_fp16.h>
#include <math.h>
#include <stdint.h>

#define DIMC 1536
#define NHEAD 12
#define HDIM 128
#define SEQ 5400
#define GHW 900
#define GWID 30

// scratch (device globals: no allocations allowed)
__device__ float  g_qf[SEQ * DIMC];
__device__ float  g_kf[SEQ * DIMC];
__device__ __half g_qh[SEQ * DIMC];
__device__ __half g_kh[SEQ * DIMC];
__device__ __half g_vt[NHEAD * HDIM * SEQ + 256];   // [head][d][seq] (+pad)
__device__ __half g_ao[SEQ * DIMC];
__device__ __half g_xh[SEQ * DIMC];
__device__ __half g_wh[4][DIMC * DIMC];

// ---------------------------------------------------------------------------
// helpers
// ---------------------------------------------------------------------------
__device__ __forceinline__ void mma_f16(float* c, const uint32_t* a,
                                        uint32_t b0, uint32_t b1) {
    asm volatile(
        "mma.sync.aligned.m16n8k16.row.col.f32.f16.f16.f32 "
        "{%0,%1,%2,%3}, {%4,%5,%6,%7}, {%8,%9}, {%0,%1,%2,%3};\n"
        : "+f"(c[0]), "+f"(c[1]), "+f"(c[2]), "+f"(c[3])
        : "r"(a[0]), "r"(a[1]), "r"(a[2]), "r"(a[3]), "r"(b0), "r"(b1));
}

__device__ __forceinline__ void ldsm4(uint32_t& r0, uint32_t& r1,
                                      uint32_t& r2, uint32_t& r3, uint32_t a) {
    asm volatile("ldmatrix.sync.aligned.m8n8.x4.shared.b16 {%0,%1,%2,%3}, [%4];"
                 : "=r"(r0), "=r"(r1), "=r"(r2), "=r"(r3) : "r"(a) : "memory");
}

__device__ __forceinline__ void sts32(uint32_t a, uint32_t v) {
    asm volatile("st.shared.b32 [%0], %1;" :: "r"(a), "r"(v) : "memory");
}

__device__ __forceinline__ void barn(int id, int cnt) {
    asm volatile("bar.sync %0, %1;" :: "r"(id), "r"(cnt) : "memory");
}

__device__ __forceinline__ void cp16(uint32_t dst, const void* src) {
    asm volatile("cp.async.cg.shared.global [%0], [%1], 16;\n"
                 :: "r"(dst), "l"(src));
}
__device__ __forceinline__ void cp_commit() {
    asm volatile("cp.async.commit_group;\n");
}
template <int N> __device__ __forceinline__ void cp_wait() {
    asm volatile("cp.async.wait_group %0;\n" :: "n"(N));
}

// exp2 on a packed pair: arg pair (fp32) -> fp16x2 -> h2exp2 -> packed P
__device__ __forceinline__ uint32_t pexp2(float a, float b, float2& fsum) {
    __half2 h = h2exp2(__floats2half2_rn(a, b));
    float2 f = __half22float2(h);
    fsum.x += f.x; fsum.y += f.y;
    return *(uint32_t*)&h;
}

// ---------------------------------------------------------------------------
// fp32 -> fp16 conversion copies
// ---------------------------------------------------------------------------
__global__ void __launch_bounds__(256) conv_h(
    const float4* __restrict__ s, __half2* __restrict__ d, int n4)
{
    int i = blockIdx.x * 256 + threadIdx.x;
    if (i < n4) {
        float4 v = s[i];
        d[2 * i + 0] = __floats2half2_rn(v.x, v.y);
        d[2 * i + 1] = __floats2half2_rn(v.z, v.w);
    }
}

__global__ void __launch_bounds__(256) conv_h4(
    const float4* __restrict__ s0, const float4* __restrict__ s1,
    const float4* __restrict__ s2, const float4* __restrict__ s3,
    __half2* __restrict__ d, int n4)
{
    const float4* s = (blockIdx.y == 0) ? s0 : (blockIdx.y == 1) ? s1
                     : (blockIdx.y == 2) ? s2 : s3;
    __half2* dd = d + (size_t)blockIdx.y * n4 * 2;
    int i = blockIdx.x * 256 + threadIdx.x;
    if (i < n4) {
        float4 v = s[i];
        dd[2 * i + 0] = __floats2half2_rn(v.x, v.y);
        dd[2 * i + 1] = __floats2half2_rn(v.z, v.w);
    }
}

// ---------------------------------------------------------------------------
// FP16 GEMM core: 128x128 tile, BK=64, 2-stage cp.async pipeline (24 k-blocks),
// ldmatrix fragments, warp tile 64x32 (8 warps 2x4).  [round-12 winner]
// ---------------------------------------------------------------------------
#define GSTRH 72                       // halves per smem row (64 + 8 pad)
#define GBUF_H (128 * GSTRH)           // halves per stage per matrix
#define GSM_BYTES (2 * GBUF_H * 2 * 2) // 73728 bytes

struct GemmCore {
    template <typename EPI>
    static __device__ __forceinline__ void run(
        const __half* __restrict__ A, const __half* __restrict__ B,
        int bm, int bn, int M, __half* gsm, EPI epi)
    {
        __half* sA = gsm;
        __half* sB = gsm + 2 * GBUF_H;
        const int tid = threadIdx.x;
        const int lane = tid & 31;
        const int wid = tid >> 5;
        const int wm = wid & 1;
        const int wn = wid >> 1;
        const uint32_t aAddr = (uint32_t)__cvta_generic_to_shared(sA);
        const uint32_t bAddr = (uint32_t)__cvta_generic_to_shared(sB);
        const uint32_t aOff = ((wm * 64 + (lane & 15)) * GSTRH + (lane >> 4) * 8) * 2;
        const uint32_t bOff = ((wn * 32 + (lane & 7) + ((lane >> 4) & 1) * 8) * GSTRH
                               + ((lane >> 3) & 1) * 8) * 2;

        float acc[4][4][4];
#pragma unroll
        for (int mt = 0; mt < 4; ++mt)
#pragma unroll
            for (int nt = 0; nt < 4; ++nt)
#pragma unroll
                for (int i = 0; i < 4; ++i) acc[mt][nt][i] = 0.f;

        auto fill = [&](int stg, int kb) {
            const int k0 = kb * 64;
            const uint32_t ab = aAddr + stg * GBUF_H * 2;
            const uint32_t bb = bAddr + stg * GBUF_H * 2;
#pragma unroll
            for (int i = 0; i < 4; ++i) {
                int c = tid + i * 256;          // 0..1023
                int r = c >> 3, c8 = c & 7;
                int ra = bm + r; if (ra > M - 1) ra = M - 1;
                cp16(ab + (r * GSTRH + 8 * c8) * 2,
                     A + (size_t)ra * DIMC + k0 + 8 * c8);
                cp16(bb + (r * GSTRH + 8 * c8) * 2,
                     B + (size_t)(bn + r) * DIMC + k0 + 8 * c8);
            }
            cp_commit();
        };

        fill(0, 0);

        const int NKB = DIMC / 64;   // 24
        for (int kb = 0; kb < NKB; ++kb) {
            const int buf = kb & 1;
            if (kb + 1 < NKB) {
                fill(buf ^ 1, kb + 1);
                cp_wait<1>();
            } else {
                cp_wait<0>();
            }
            __syncthreads();

            const uint32_t ab = aAddr + buf * GBUF_H * 2 + aOff;
            const uint32_t bb = bAddr + buf * GBUF_H * 2 + bOff;
#pragma unroll
            for (int ks = 0; ks < 4; ++ks) {
                uint32_t af[4][4], bf[2][4];
#pragma unroll
                for (int mt = 0; mt < 4; ++mt)
                    ldsm4(af[mt][0], af[mt][1], af[mt][2], af[mt][3],
                          ab + (mt * 16 * GSTRH + ks * 16) * 2);
#pragma unroll
                for (int p = 0; p < 2; ++p)
                    ldsm4(bf[p][0], bf[p][1], bf[p][2], bf[p][3],
                          bb + (p * 16 * GSTRH + ks * 16) * 2);
#pragma unroll
                for (int mt = 0; mt < 4; ++mt)
#pragma unroll
                    for (int p = 0; p < 2; ++p) {
                        mma_f16(acc[mt][2 * p],     af[mt], bf[p][0], bf[p][1]);
                        mma_f16(acc[mt][2 * p + 1], af[mt], bf[p][2], bf[p][3]);
                    }
            }
            __syncthreads();
        }
        epi(acc);
    }
};

__global__ void __launch_bounds__(256, 2) gemm_qkv(
    const __half* __restrict__ A, const __half* __restrict__ W,
    const float* __restrict__ qb, const float* __restrict__ kb_,
    const float* __restrict__ vb,
    float* __restrict__ Cq, float* __restrict__ Ck,
    __half* __restrict__ Vt, int M)
{
    extern __shared__ __half gsm[];
    const int z = blockIdx.z;
    const int tid = threadIdx.x;
    const int lane = tid & 31;
    const int wid = tid >> 5;
    const int gid = lane >> 2;
    const int tig = lane & 3;
    const int wm = wid & 1;
    const int wn = wid >> 1;
    const int bm = blockIdx.y * 128;
    const int bn = blockIdx.x * 128;
    const __half* B = W + (size_t)z * DIMC * DIMC;
    const float* bias = (z == 0) ? qb : (z == 1) ? kb_ : vb;
    float* Cf = (z == 0) ? Cq : Ck;

    GemmCore::run(A, B, bm, bn, M, gsm, [&](float acc[4][4][4]) {
#pragma unroll
        for (int mt = 0; mt < 4; ++mt) {
            int r0 = bm + wm * 64 + mt * 16 + gid;
            int r1 = r0 + 8;
#pragma unroll
            for (int nt = 0; nt < 4; ++nt) {
                int col = bn + wn * 32 + nt * 8 + 2 * tig;
                float b0 = __ldg(bias + col), b1 = __ldg(bias + col + 1);
                if (z < 2) {
                    if (r0 < M)
                        *(float2*)(Cf + (size_t)r0 * DIMC + col) =
                            make_float2(acc[mt][nt][0] + b0, acc[mt][nt][1] + b1);
                    if (r1 < M)
                        *(float2*)(Cf + (size_t)r1 * DIMC + col) =
                            make_float2(acc[mt][nt][2] + b0, acc[mt][nt][3] + b1);
                } else {
                    if (r0 < M) {
                        Vt[(size_t)col * SEQ + r0]       = __float2half_rn(acc[mt][nt][0] + b0);
                        Vt[(size_t)(col + 1) * SEQ + r0] = __float2half_rn(acc[mt][nt][1] + b1);
                    }
                    if (r1 < M) {
                        Vt[(size_t)col * SEQ + r1]       = __float2half_rn(acc[mt][nt][2] + b0);
                        Vt[(size_t)(col + 1) * SEQ + r1] = __float2half_rn(acc[mt][nt][3] + b1);
                    }
                }
            }
        }
    });
}

__global__ void __launch_bounds__(256, 2) gemm_o(
    const __half* __restrict__ A, const __half* __restrict__ B,
    const float* __restrict__ bias, float* __restrict__ Cf, int M)
{
    extern __shared__ __half gsm[];
    const int tid = threadIdx.x;
    const int lane = tid & 31;
    const int wid = tid >> 5;
    const int gid = lane >> 2;
    const int tig = lane & 3;
    const int wm = wid & 1;
    const int wn = wid >> 1;
    const int bm = blockIdx.y * 128;
    const int bn = blockIdx.x * 128;

    GemmCore::run(A, B, bm, bn, M, gsm, [&](float acc[4][4][4]) {
#pragma unroll
        for (int mt = 0; mt < 4; ++mt) {
            int r0 = bm + wm * 64 + mt * 16 + gid;
            int r1 = r0 + 8;
#pragma unroll
            for (int nt = 0; nt < 4; ++nt) {
                int col = bn + wn * 32 + nt * 8 + 2 * tig;
                float b0 = __ldg(bias + col), b1 = __ldg(bias + col + 1);
                if (r0 < M)
                    *(float2*)(Cf + (size_t)r0 * DIMC + col) =
                        make_float2(acc[mt][nt][0] + b0, acc[mt][nt][1] + b1);
                if (r1 < M)
                    *(float2*)(Cf + (size_t)r1 * DIMC + col) =
                        make_float2(acc[mt][nt][2] + b0, acc[mt][nt][3] + b1);
            }
        }
    });
}

// ---------------------------------------------------------------------------
// Fused RMSNorm + RoPE: reads fp32 q/k projections, writes fp16.
// q pre-scaled by log2(e)/sqrt(HD)  (QK scores come out in log2 domain).
// ---------------------------------------------------------------------------
__global__ void __launch_bounds__(256) norm_rope_kernel(
    const float* __restrict__ nqw, const float* __restrict__ nkw,
    const float* __restrict__ cosT, const float* __restrict__ sinT)
{
    __shared__ float buf[DIMC];
    __shared__ float red[8];
    const int row = blockIdx.x;
    const float* src = blockIdx.y ? g_kf : g_qf;
    __half* dst = blockIdx.y ? g_kh : g_qh;
    const float* w = blockIdx.y ? nkw : nqw;
    const float sc = blockIdx.y ? 1.0f
                   : (0.08838834764831845f * 1.4426950408889634f);
    const int tid = threadIdx.x;

    float ss = 0.f;
#pragma unroll
    for (int j = tid; j < DIMC; j += 256) {
        float v = src[(size_t)row * DIMC + j];
        buf[j] = v;
        ss += v * v;
    }
#pragma unroll
    for (int o = 16; o; o >>= 1) ss += __shfl_xor_sync(0xffffffffu, ss, o);
    if ((tid & 31) == 0) red[tid >> 5] = ss;
    __syncthreads();
    float tot = 0.f;
#pragma unroll
    for (int i = 0; i < 8; ++i) tot += red[i];
    const float rms = rsqrtf(tot * (1.0f / DIMC) + 1e-6f);
#pragma unroll
    for (int j = tid; j < DIMC; j += 256) buf[j] = buf[j] * rms * w[j];
    __syncthreads();

    const int f = row / GHW;
    const int rem = row - f * GHW;
    const int h = rem / GWID;
    const int ww = rem - h * GWID;
#pragma unroll
    for (int p = tid; p < DIMC / 2; p += 256) {
        int n = p >> 6;
        int i = p & 63;
        int pos = (i < 22) ? f : (i < 43) ? h : ww;
        float c = cosT[pos * 64 + i];
        float s = sinT[pos * 64 + i];
        int idx = n * HDIM + 2 * i;
        float xr = buf[idx], xi = buf[idx + 1];
        *(__half2*)(dst + (size_t)row * DIMC + idx) =
            __floats2half2_rn((xr * c - xi * s) * sc,
                              (xr * s + xi * c) * sc);
    }
}

// ---------------------------------------------------------------------------
// Flash attention (round-12 structure + deferred l-exchange, fixed sync):
// 4(m) x 2(n) warps, BQ=128, BK=64, 256 threads, 2 CTAs/SM.
// exp2-domain softmax. Per tile: exM barrier + bare P-ordering barrier.
// l kept as per-thread OWN-HALF partials; combined once in the epilogue.
// V prefetch at tile top; K refilled post-QK.
// ---------------------------------------------------------------------------
#define AKSTR 136
#define AVSTR 72
#define APSTR 72
#define AQ_H 0
#define AK_H 17408
#define AV_H 26112
#define AP_H 44544
#define AEX_B (53760 * 2)
#define AEXS_B (AEX_B + 1024)
#define ATT_SMEM_BYTES 109568

__global__ void __launch_bounds__(256, 2) attn_mma()
{
    extern __shared__ __half smh[];
    const uint32_t base = (uint32_t)__cvta_generic_to_shared(smh);
    const uint32_t Qb = base;
    const uint32_t Kb = base + AK_H * 2;
    const uint32_t Vb = base + AV_H * 2;
    const uint32_t Pb = base + AP_H * 2;
    float* exM = (float*)((char*)smh + AEX_B);
    float* exS = (float*)((char*)smh + AEXS_B);

    const int tid = threadIdx.x;
    const int lane = tid & 31;
    const int w = tid >> 5;
    const int wm = w & 3;
    const int wn = w >> 2;
    const int gid = lane >> 2;
    const int tig = lane & 3;
    const int qrow = wm * 32;
    const int q0 = blockIdx.x * 128;
    const int head = blockIdx.y;
    const int hoff = head * HDIM;

    const int aRow = lane & 15;
    const int aCol = (lane >> 4) * 8;
    const uint32_t qOff0 = ((qrow + aRow) * AKSTR + aCol) * 2;
    const uint32_t qOff1 = qOff0 + 16 * AKSTR * 2;
    const uint32_t pOff0 = ((qrow + aRow) * APSTR + aCol) * 2;
    const uint32_t pOff1 = pOff0 + 16 * APSTR * 2;
    const int bRow = (lane & 7) + ((lane >> 4) & 1) * 8;
    const int bCol = ((lane >> 3) & 1) * 8;
    const uint32_t kOff = ((wn * 32 + bRow) * AKSTR + bCol) * 2;
    const uint32_t vOff = ((wn * 64 + bRow) * AVSTR + bCol) * 2;

    // ---- initial fills: Q (persistent), K(0), V(0) ----
#pragma unroll
    for (int i = 0; i < 8; ++i) {
        int c = tid + i * 256;
        int r = c >> 4, c16 = c & 15;
        int sr = q0 + r; if (sr > SEQ - 1) sr = SEQ - 1;
        cp16(Qb + (r * AKSTR + 8 * c16) * 2,
             g_qh + (size_t)sr * DIMC + hoff + 8 * c16);
    }
    auto fillK = [&](int k0) {
#pragma unroll
        for (int i = 0; i < 4; ++i) {
            int c = tid + i * 256;
            int r = c >> 4, c16 = c & 15;
            int sr = k0 + r; if (sr > SEQ - 1) sr = SEQ - 1;
            cp16(Kb + (r * AKSTR + 8 * c16) * 2,
                 g_kh + (size_t)sr * DIMC + hoff + 8 * c16);
        }
    };
    auto fillV = [&](int buf, int k0) {
#pragma unroll
        for (int i = 0; i < 4; ++i) {
            int c = tid + i * 256;
            int r = c >> 3, c8 = c & 7;
            cp16(Vb + (buf * 128 * AVSTR + r * AVSTR + 8 * c8) * 2,
                 g_vt + (size_t)(hoff + r) * SEQ + k0 + 8 * c8);
        }
    };
    fillK(0);
    fillV(0, 0);
    cp_commit();

    float oacc[2][8][4];
#pragma unroll
    for (int mq = 0; mq < 2; ++mq)
#pragma unroll
        for (int dt = 0; dt < 8; ++dt)
#pragma unroll
            for (int i = 0; i < 4; ++i) oacc[mq][dt][i] = 0.f;
    float m[2][2] = {{-1e30f, -1e30f}, {-1e30f, -1e30f}};
    float l[2][2] = {{0.f, 0.f}, {0.f, 0.f}};   // per-thread OWN-HALF partials

    const int nkt = (SEQ + 63) / 64;   // 85
    for (int kt = 0; kt < nkt; ++kt) {
        const int buf = kt & 1;
        const int k0 = kt * 64;
        cp_wait<0>();
        __syncthreads();      // orders ALL cross-tile hazards (K,V,P,exM)

        // ---- V(t+1) prefetch ----
        if (kt + 1 < nkt) fillV(buf ^ 1, k0 + 64);

        // ---- S = Q K^T (scores in log2 domain; Q pre-scaled) ----
        float sacc[2][4][4];
#pragma unroll
        for (int mq = 0; mq < 2; ++mq)
#pragma unroll
            for (int nt = 0; nt < 4; ++nt)
#pragma unroll
                for (int i = 0; i < 4; ++i) sacc[mq][nt][i] = 0.f;

#pragma unroll
        for (int ks = 0; ks < 8; ++ks) {
            uint32_t qa0[4], qa1[4];
            ldsm4(qa0[0], qa0[1], qa0[2], qa0[3], Qb + qOff0 + ks * 32);
            ldsm4(qa1[0], qa1[1], qa1[2], qa1[3], Qb + qOff1 + ks * 32);
#pragma unroll
            for (int p = 0; p < 2; ++p) {
                uint32_t b0, b1, b2, b3;
                ldsm4(b0, b1, b2, b3, Kb + kOff + (p * 16 * AKSTR + ks * 16) * 2);
                mma_f16(sacc[0][2 * p],     qa0, b0, b1);
                mma_f16(sacc[0][2 * p + 1], qa0, b2, b3);
                mma_f16(sacc[1][2 * p],     qa1, b0, b1);
                mma_f16(sacc[1][2 * p + 1], qa1, b2, b3);
            }
        }

        __syncthreads();      // all warps done reading K -> safe to refill
        if (kt + 1 < nkt) fillK(k0 + 64);
        cp_commit();          // one group: V(t+1) + K(t+1)

        // ---- mask tail keys (warp's slice) ----
        const int krem = SEQ - k0 - wn * 32;
        if (krem < 32) {
#pragma unroll
            for (int mq = 0; mq < 2; ++mq)
#pragma unroll
                for (int nt = 0; nt < 4; ++nt) {
                    int c = nt * 8 + 2 * tig;
                    if (c >= krem)     { sacc[mq][nt][0] = -1e30f; sacc[mq][nt][2] = -1e30f; }
                    if (c + 1 >= krem) { sacc[mq][nt][1] = -1e30f; sacc[mq][nt][3] = -1e30f; }
                }
        }

        // ---- partial row max + cross-warp combine ----
        float mx[2][2] = {{-1e30f, -1e30f}, {-1e30f, -1e30f}};
#pragma unroll
        for (int mq = 0; mq < 2; ++mq)
#pragma unroll
            for (int nt = 0; nt < 4; ++nt) {
                mx[mq][0] = fmaxf(mx[mq][0], fmaxf(sacc[mq][nt][0], sacc[mq][nt][1]));
                mx[mq][1] = fmaxf(mx[mq][1], fmaxf(sacc[mq][nt][2], sacc[mq][nt][3]));
            }
#pragma unroll
        for (int mq = 0; mq < 2; ++mq)
#pragma unroll
            for (int h = 0; h < 2; ++h) {
                mx[mq][h] = fmaxf(mx[mq][h], __shfl_xor_sync(0xffffffffu, mx[mq][h], 1));
                mx[mq][h] = fmaxf(mx[mq][h], __shfl_xor_sync(0xffffffffu, mx[mq][h], 2));
            }
        if (tig == 0) {
#pragma unroll
            for (int mq = 0; mq < 2; ++mq) {
                exM[wn * 128 + qrow + mq * 16 + gid]     = mx[mq][0];
                exM[wn * 128 + qrow + mq * 16 + gid + 8] = mx[mq][1];
            }
        }
        barn(1 + wm, 64);

        float f[2][2];
#pragma unroll
        for (int mq = 0; mq < 2; ++mq)
#pragma unroll
            for (int h = 0; h < 2; ++h) {
                float oth = exM[(wn ^ 1) * 128 + qrow + mq * 16 + gid + h * 8];
                float mn = fmaxf(m[mq][h], fmaxf(mx[mq][h], oth));
                f[mq][h] = exp2f(m[mq][h] - mn);
                m[mq][h] = mn;
            }

        // ---- P = exp2(s - m) fp16 pairs; own-half per-thread partial sums ----
        float2 ps2[2][2] = {{{0.f,0.f},{0.f,0.f}}, {{0.f,0.f},{0.f,0.f}}};
        uint32_t ph[2][2][4];
#pragma unroll
        for (int mq = 0; mq < 2; ++mq) {
#pragma unroll
            for (int nt = 0; nt < 4; ++nt) {
                int kc = nt >> 1, o = (nt & 1) * 2;
                ph[mq][kc][o] = pexp2(sacc[mq][nt][0] - m[mq][0],
                                      sacc[mq][nt][1] - m[mq][0], ps2[mq][0]);
                ph[mq][kc][o + 1] = pexp2(sacc[mq][nt][2] - m[mq][1],
                                          sacc[mq][nt][3] - m[mq][1], ps2[mq][1]);
            }
#pragma unroll
            for (int kc = 0; kc < 2; ++kc) {
                uint32_t pr = Pb + ((qrow + mq * 16 + gid) * APSTR
                                    + wn * 32 + kc * 16 + 2 * tig) * 2;
                sts32(pr,                      ph[mq][kc][0]);
                sts32(pr + 8 * APSTR * 2,      ph[mq][kc][1]);
                sts32(pr + 16,                 ph[mq][kc][2]);
                sts32(pr + 8 * APSTR * 2 + 16, ph[mq][kc][3]);
            }
        }
        // l: per-thread own-half partial only (f identical across halves;
        // cross-half combine deferred to the epilogue)
#pragma unroll
        for (int mq = 0; mq < 2; ++mq)
#pragma unroll
            for (int h = 0; h < 2; ++h)
                l[mq][h] = l[mq][h] * f[mq][h] + ps2[mq][h].x + ps2[mq][h].y;

#pragma unroll
        for (int mq = 0; mq < 2; ++mq)
#pragma unroll
            for (int dt = 0; dt < 8; ++dt) {
                oacc[mq][dt][0] *= f[mq][0]; oacc[mq][dt][1] *= f[mq][0];
                oacc[mq][dt][2] *= f[mq][1]; oacc[mq][dt][3] *= f[mq][1];
            }

        // ---- bare pair barrier: P stores visible before cross-half reads ----
        barn(1 + wm, 64);

        // ---- O += P V (32 rows x 64 d per warp, all 64 keys) ----
        const uint32_t vbA = Vb + buf * 128 * AVSTR * 2 + vOff;
#pragma unroll
        for (int kc = 0; kc < 4; ++kc) {
            uint32_t pa0[4], pa1[4];
            if ((kc >> 1) == wn) {
#pragma unroll
                for (int i = 0; i < 4; ++i) {
                    pa0[i] = ph[0][kc & 1][i];
                    pa1[i] = ph[1][kc & 1][i];
                }
            } else {
                ldsm4(pa0[0], pa0[1], pa0[2], pa0[3], Pb + pOff0 + kc * 32);
                ldsm4(pa1[0], pa1[1], pa1[2], pa1[3], Pb + pOff1 + kc * 32);
            }
#pragma unroll
            for (int p = 0; p < 4; ++p) {
                uint32_t v0, v1, v2, v3;
                ldsm4(v0, v1, v2, v3, vbA + (p * 16 * AVSTR + kc * 16) * 2);
                mma_f16(oacc[0][2 * p],     pa0, v0, v1);
                mma_f16(oacc[0][2 * p + 1], pa0, v2, v3);
                mma_f16(oacc[1][2 * p],     pa1, v0, v1);
                mma_f16(oacc[1][2 * p + 1], pa1, v2, v3);
            }
        }
        // no bottom sync: top-of-tile __syncthreads orders all reuse
    }

    // ---- epilogue: combine l across quad, then across key-half warps ----
#pragma unroll
    for (int mq = 0; mq < 2; ++mq)
#pragma unroll
        for (int h = 0; h < 2; ++h) {
            l[mq][h] += __shfl_xor_sync(0xffffffffu, l[mq][h], 1);
            l[mq][h] += __shfl_xor_sync(0xffffffffu, l[mq][h], 2);
        }
    if (tig == 0) {
#pragma unroll
        for (int mq = 0; mq < 2; ++mq) {
            exS[wn * 128 + qrow + mq * 16 + gid]     = l[mq][0];
            exS[wn * 128 + qrow + mq * 16 + gid + 8] = l[mq][1];
        }
    }
    barn(1 + wm, 64);

#pragma unroll
    for (int mq = 0; mq < 2; ++mq) {
        float lt0 = l[mq][0] + exS[(wn ^ 1) * 128 + qrow + mq * 16 + gid];
        float lt1 = l[mq][1] + exS[(wn ^ 1) * 128 + qrow + mq * 16 + gid + 8];
        float inv0 = 1.f / lt0, inv1 = 1.f / lt1;
        int r0 = q0 + qrow + mq * 16 + gid;
        int r1 = r0 + 8;
#pragma unroll
        for (int dt = 0; dt < 8; ++dt) {
            int col = hoff + wn * 64 + dt * 8 + 2 * tig;
            if (r0 < SEQ)
                *(__half2*)(g_ao + (size_t)r0 * DIMC + col) =
                    __floats2half2_rn(oacc[mq][dt][0] * inv0, oacc[mq][dt][1] * inv0);
            if (r1 < SEQ)
                *(__half2*)(g_ao + (size_t)r1 * DIMC + col) =
                    __floats2half2_rn(oacc[mq][dt][2] * inv1, oacc[mq][dt][3] * inv1);
        }
    }
}

// ---------------------------------------------------------------------------
extern "C" void kernel_launch(void* const* d_in, const int* in_sizes, int n_in,
                              void* d_out, int out_size)
{
    const float* x    = (const float*)d_in[0];
    const float* q_b  = (const float*)d_in[2];
    const float* k_b  = (const float*)d_in[4];
    const float* v_b  = (const float*)d_in[6];
    const float* o_b  = (const float*)d_in[8];
    const float* nqw  = (const float*)d_in[9];
    const float* nkw  = (const float*)d_in[10];
    const float* cosT = (const float*)d_in[11];
    const float* sinT = (const float*)d_in[12];
    float* out = (float*)d_out;

    float *dqf, *dkf;
    __half *dvt, *dxh, *dwh, *dao;
    cudaGetSymbolAddress((void**)&dqf, g_qf);
    cudaGetSymbolAddress((void**)&dkf, g_kf);
    cudaGetSymbolAddress((void**)&dvt, g_vt);
    cudaGetSymbolAddress((void**)&dxh, g_xh);
    cudaGetSymbolAddress((void**)&dwh, g_wh);
    cudaGetSymbolAddress((void**)&dao, g_ao);

    // convert inputs to fp16
    const int nx4 = SEQ * DIMC / 4;
    const int nw4 = DIMC * DIMC / 4;
    conv_h<<<(nx4 + 255) / 256, 256>>>((const float4*)x, (__half2*)dxh, nx4);
    conv_h4<<<dim3((nw4 + 255) / 256, 4), 256>>>(
        (const float4*)d_in[1], (const float4*)d_in[3],
        (const float4*)d_in[5], (const float4*)d_in[7],
        (__half2*)dwh, nw4);

    cudaFuncSetAttribute(gemm_qkv,
                         cudaFuncAttributeMaxDynamicSharedMemorySize, GSM_BYTES);
    cudaFuncSetAttribute(gemm_o,
                         cudaFuncAttributeMaxDynamicSharedMemorySize, GSM_BYTES);

    dim3 gQKV(DIMC / 128, (SEQ + 127) / 128, 3);
    gemm_qkv<<<gQKV, 256, GSM_BYTES>>>(dxh, dwh, q_b, k_b, v_b,
                                       dqf, dkf, dvt, SEQ);

    norm_rope_kernel<<<dim3(SEQ, 2), 256>>>(nqw, nkw, cosT, sinT);

    cudaFuncSetAttribute(attn_mma,
                         cudaFuncAttributeMaxDynamicSharedMemorySize, ATT_SMEM_BYTES);
    attn_mma<<<dim3((SEQ + 127) / 128, NHEAD), 256, ATT_SMEM_BYTES>>>();

    dim3 gGemm(DIMC / 128, (SEQ + 127) / 128);
    gemm_o<<<gGemm, 256, GSM_BYTES>>>(dao, dwh + 3 * (size_t)DIMC * DIMC,
                                      o_b, out, SEQ);
}

// round 16
// speedup vs baseline: 1.1478x; 1.0695x over previous
#include <cuda_runtime.h>
#include <cuda_fp16.h>
#include <math.h>
#include <stdint.h>

#define DIMC 1536
#define NHEAD 12
#define HDIM 128
#define SEQ 5400
#define GHW 900
#define GWID 30

// scratch (device globals: no allocations allowed)
__device__ float  g_qf[SEQ * DIMC];
__device__ float  g_kf[SEQ * DIMC];
__device__ __half g_qh[SEQ * DIMC];
__device__ __half g_kh[SEQ * DIMC];
__device__ __half g_vt[NHEAD * HDIM * SEQ + 256];   // [head][d][seq] (+pad)
__device__ __half g_ao[SEQ * DIMC];
__device__ __half g_xh[SEQ * DIMC];
__device__ __half g_wh[4][DIMC * DIMC];

// ---------------------------------------------------------------------------
// helpers
// ---------------------------------------------------------------------------
__device__ __forceinline__ void mma_f16(float* c, const uint32_t* a,
                                        uint32_t b0, uint32_t b1) {
    asm volatile(
        "mma.sync.aligned.m16n8k16.row.col.f32.f16.f16.f32 "
        "{%0,%1,%2,%3}, {%4,%5,%6,%7}, {%8,%9}, {%0,%1,%2,%3};\n"
        : "+f"(c[0]), "+f"(c[1]), "+f"(c[2]), "+f"(c[3])
        : "r"(a[0]), "r"(a[1]), "r"(a[2]), "r"(a[3]), "r"(b0), "r"(b1));
}

__device__ __forceinline__ void ldsm4(uint32_t& r0, uint32_t& r1,
                                      uint32_t& r2, uint32_t& r3, uint32_t a) {
    asm volatile("ldmatrix.sync.aligned.m8n8.x4.shared.b16 {%0,%1,%2,%3}, [%4];"
                 : "=r"(r0), "=r"(r1), "=r"(r2), "=r"(r3) : "r"(a) : "memory");
}

__device__ __forceinline__ void sts32(uint32_t a, uint32_t v) {
    asm volatile("st.shared.b32 [%0], %1;" :: "r"(a), "r"(v) : "memory");
}

__device__ __forceinline__ void barn(int id, int cnt) {
    asm volatile("bar.sync %0, %1;" :: "r"(id), "r"(cnt) : "memory");
}

__device__ __forceinline__ void cp16(uint32_t dst, const void* src) {
    asm volatile("cp.async.cg.shared.global [%0], [%1], 16;\n"
                 :: "r"(dst), "l"(src));
}
__device__ __forceinline__ void cp_commit() {
    asm volatile("cp.async.commit_group;\n");
}
template <int N> __device__ __forceinline__ void cp_wait() {
    asm volatile("cp.async.wait_group %0;\n" :: "n"(N));
}

// exp2 on a packed pair: arg pair (fp32) -> fp16x2 -> h2exp2 -> packed P
__device__ __forceinline__ uint32_t pexp2(float a, float b, float2& fsum) {
    __half2 h = h2exp2(__floats2half2_rn(a, b));
    float2 f = __half22float2(h);
    fsum.x += f.x; fsum.y += f.y;
    return *(uint32_t*)&h;
}

// ---------------------------------------------------------------------------
// fp32 -> fp16 conversion copies
// ---------------------------------------------------------------------------
__global__ void __launch_bounds__(256) conv_h(
    const float4* __restrict__ s, __half2* __restrict__ d, int n4)
{
    int i = blockIdx.x * 256 + threadIdx.x;
    if (i < n4) {
        float4 v = s[i];
        d[2 * i + 0] = __floats2half2_rn(v.x, v.y);
        d[2 * i + 1] = __floats2half2_rn(v.z, v.w);
    }
}

__global__ void __launch_bounds__(256) conv_h4(
    const float4* __restrict__ s0, const float4* __restrict__ s1,
    const float4* __restrict__ s2, const float4* __restrict__ s3,
    __half2* __restrict__ d, int n4)
{
    const float4* s = (blockIdx.y == 0) ? s0 : (blockIdx.y == 1) ? s1
                     : (blockIdx.y == 2) ? s2 : s3;
    __half2* dd = d + (size_t)blockIdx.y * n4 * 2;
    int i = blockIdx.x * 256 + threadIdx.x;
    if (i < n4) {
        float4 v = s[i];
        dd[2 * i + 0] = __floats2half2_rn(v.x, v.y);
        dd[2 * i + 1] = __floats2half2_rn(v.z, v.w);
    }
}

// ---------------------------------------------------------------------------
// FP16 GEMM core: 128x128 tile, BK=64, 2-stage cp.async pipeline (24 k-blocks),
// ldmatrix fragments, warp tile 64x32 (8 warps 2x4).  [round-12 winner]
// ---------------------------------------------------------------------------
#define GSTRH 72                       // halves per smem row (64 + 8 pad)
#define GBUF_H (128 * GSTRH)           // halves per stage per matrix
#define GSM_BYTES (2 * GBUF_H * 2 * 2) // 73728 bytes

struct GemmCore {
    template <typename EPI>
    static __device__ __forceinline__ void run(
        const __half* __restrict__ A, const __half* __restrict__ B,
        int bm, int bn, int M, __half* gsm, EPI epi)
    {
        __half* sA = gsm;
        __half* sB = gsm + 2 * GBUF_H;
        const int tid = threadIdx.x;
        const int lane = tid & 31;
        const int wid = tid >> 5;
        const int wm = wid & 1;
        const int wn = wid >> 1;
        const uint32_t aAddr = (uint32_t)__cvta_generic_to_shared(sA);
        const uint32_t bAddr = (uint32_t)__cvta_generic_to_shared(sB);
        const uint32_t aOff = ((wm * 64 + (lane & 15)) * GSTRH + (lane >> 4) * 8) * 2;
        const uint32_t bOff = ((wn * 32 + (lane & 7) + ((lane >> 4) & 1) * 8) * GSTRH
                               + ((lane >> 3) & 1) * 8) * 2;

        float acc[4][4][4];
#pragma unroll
        for (int mt = 0; mt < 4; ++mt)
#pragma unroll
            for (int nt = 0; nt < 4; ++nt)
#pragma unroll
                for (int i = 0; i < 4; ++i) acc[mt][nt][i] = 0.f;

        auto fill = [&](int stg, int kb) {
            const int k0 = kb * 64;
            const uint32_t ab = aAddr + stg * GBUF_H * 2;
            const uint32_t bb = bAddr + stg * GBUF_H * 2;
#pragma unroll
            for (int i = 0; i < 4; ++i) {
                int c = tid + i * 256;          // 0..1023
                int r = c >> 3, c8 = c & 7;
                int ra = bm + r; if (ra > M - 1) ra = M - 1;
                cp16(ab + (r * GSTRH + 8 * c8) * 2,
                     A + (size_t)ra * DIMC + k0 + 8 * c8);
                cp16(bb + (r * GSTRH + 8 * c8) * 2,
                     B + (size_t)(bn + r) * DIMC + k0 + 8 * c8);
            }
            cp_commit();
        };

        fill(0, 0);

        const int NKB = DIMC / 64;   // 24
        for (int kb = 0; kb < NKB; ++kb) {
            const int buf = kb & 1;
            if (kb + 1 < NKB) {
                fill(buf ^ 1, kb + 1);
                cp_wait<1>();
            } else {
                cp_wait<0>();
            }
            __syncthreads();

            const uint32_t ab = aAddr + buf * GBUF_H * 2 + aOff;
            const uint32_t bb = bAddr + buf * GBUF_H * 2 + bOff;
#pragma unroll
            for (int ks = 0; ks < 4; ++ks) {
                uint32_t af[4][4], bf[2][4];
#pragma unroll
                for (int mt = 0; mt < 4; ++mt)
                    ldsm4(af[mt][0], af[mt][1], af[mt][2], af[mt][3],
                          ab + (mt * 16 * GSTRH + ks * 16) * 2);
#pragma unroll
                for (int p = 0; p < 2; ++p)
                    ldsm4(bf[p][0], bf[p][1], bf[p][2], bf[p][3],
                          bb + (p * 16 * GSTRH + ks * 16) * 2);
#pragma unroll
                for (int mt = 0; mt < 4; ++mt)
#pragma unroll
                    for (int p = 0; p < 2; ++p) {
                        mma_f16(acc[mt][2 * p],     af[mt], bf[p][0], bf[p][1]);
                        mma_f16(acc[mt][2 * p + 1], af[mt], bf[p][2], bf[p][3]);
                    }
            }
            __syncthreads();
        }
        epi(acc);
    }
};

__global__ void __launch_bounds__(256, 2) gemm_qkv(
    const __half* __restrict__ A, const __half* __restrict__ W,
    const float* __restrict__ qb, const float* __restrict__ kb_,
    const float* __restrict__ vb,
    float* __restrict__ Cq, float* __restrict__ Ck,
    __half* __restrict__ Vt, int M)
{
    extern __shared__ __half gsm[];
    const int z = blockIdx.z;
    const int tid = threadIdx.x;
    const int lane = tid & 31;
    const int wid = tid >> 5;
    const int gid = lane >> 2;
    const int tig = lane & 3;
    const int wm = wid & 1;
    const int wn = wid >> 1;
    const int bm = blockIdx.y * 128;
    const int bn = blockIdx.x * 128;
    const __half* B = W + (size_t)z * DIMC * DIMC;
    const float* bias = (z == 0) ? qb : (z == 1) ? kb_ : vb;
    float* Cf = (z == 0) ? Cq : Ck;

    GemmCore::run(A, B, bm, bn, M, gsm, [&](float acc[4][4][4]) {
#pragma unroll
        for (int mt = 0; mt < 4; ++mt) {
            int r0 = bm + wm * 64 + mt * 16 + gid;
            int r1 = r0 + 8;
#pragma unroll
            for (int nt = 0; nt < 4; ++nt) {
                int col = bn + wn * 32 + nt * 8 + 2 * tig;
                float b0 = __ldg(bias + col), b1 = __ldg(bias + col + 1);
                if (z < 2) {
                    if (r0 < M)
                        *(float2*)(Cf + (size_t)r0 * DIMC + col) =
                            make_float2(acc[mt][nt][0] + b0, acc[mt][nt][1] + b1);
                    if (r1 < M)
                        *(float2*)(Cf + (size_t)r1 * DIMC + col) =
                            make_float2(acc[mt][nt][2] + b0, acc[mt][nt][3] + b1);
                } else {
                    if (r0 < M) {
                        Vt[(size_t)col * SEQ + r0]       = __float2half_rn(acc[mt][nt][0] + b0);
                        Vt[(size_t)(col + 1) * SEQ + r0] = __float2half_rn(acc[mt][nt][1] + b1);
                    }
                    if (r1 < M) {
                        Vt[(size_t)col * SEQ + r1]       = __float2half_rn(acc[mt][nt][2] + b0);
                        Vt[(size_t)(col + 1) * SEQ + r1] = __float2half_rn(acc[mt][nt][3] + b1);
                    }
                }
            }
        }
    });
}

__global__ void __launch_bounds__(256, 2) gemm_o(
    const __half* __restrict__ A, const __half* __restrict__ B,
    const float* __restrict__ bias, float* __restrict__ Cf, int M)
{
    extern __shared__ __half gsm[];
    const int tid = threadIdx.x;
    const int lane = tid & 31;
    const int wid = tid >> 5;
    const int gid = lane >> 2;
    const int tig = lane & 3;
    const int wm = wid & 1;
    const int wn = wid >> 1;
    const int bm = blockIdx.y * 128;
    const int bn = blockIdx.x * 128;

    GemmCore::run(A, B, bm, bn, M, gsm, [&](float acc[4][4][4]) {
#pragma unroll
        for (int mt = 0; mt < 4; ++mt) {
            int r0 = bm + wm * 64 + mt * 16 + gid;
            int r1 = r0 + 8;
#pragma unroll
            for (int nt = 0; nt < 4; ++nt) {
                int col = bn + wn * 32 + nt * 8 + 2 * tig;
                float b0 = __ldg(bias + col), b1 = __ldg(bias + col + 1);
                if (r0 < M)
                    *(float2*)(Cf + (size_t)r0 * DIMC + col) =
                        make_float2(acc[mt][nt][0] + b0, acc[mt][nt][1] + b1);
                if (r1 < M)
                    *(float2*)(Cf + (size_t)r1 * DIMC + col) =
                        make_float2(acc[mt][nt][2] + b0, acc[mt][nt][3] + b1);
            }
        }
    });
}

// ---------------------------------------------------------------------------
// Fused RMSNorm + RoPE: reads fp32 q/k projections, writes fp16.
// q pre-scaled by log2(e)/sqrt(HD)  (QK scores come out in log2 domain).
// ---------------------------------------------------------------------------
__global__ void __launch_bounds__(256) norm_rope_kernel(
    const float* __restrict__ nqw, const float* __restrict__ nkw,
    const float* __restrict__ cosT, const float* __restrict__ sinT)
{
    __shared__ float buf[DIMC];
    __shared__ float red[8];
    const int row = blockIdx.x;
    const float* src = blockIdx.y ? g_kf : g_qf;
    __half* dst = blockIdx.y ? g_kh : g_qh;
    const float* w = blockIdx.y ? nkw : nqw;
    const float sc = blockIdx.y ? 1.0f
                   : (0.08838834764831845f * 1.4426950408889634f);
    const int tid = threadIdx.x;

    float ss = 0.f;
#pragma unroll
    for (int j = tid; j < DIMC; j += 256) {
        float v = src[(size_t)row * DIMC + j];
        buf[j] = v;
        ss += v * v;
    }
#pragma unroll
    for (int o = 16; o; o >>= 1) ss += __shfl_xor_sync(0xffffffffu, ss, o);
    if ((tid & 31) == 0) red[tid >> 5] = ss;
    __syncthreads();
    float tot = 0.f;
#pragma unroll
    for (int i = 0; i < 8; ++i) tot += red[i];
    const float rms = rsqrtf(tot * (1.0f / DIMC) + 1e-6f);
#pragma unroll
    for (int j = tid; j < DIMC; j += 256) buf[j] = buf[j] * rms * w[j];
    __syncthreads();

    const int f = row / GHW;
    const int rem = row - f * GHW;
    const int h = rem / GWID;
    const int ww = rem - h * GWID;
#pragma unroll
    for (int p = tid; p < DIMC / 2; p += 256) {
        int n = p >> 6;
        int i = p & 63;
        int pos = (i < 22) ? f : (i < 43) ? h : ww;
        float c = cosT[pos * 64 + i];
        float s = sinT[pos * 64 + i];
        int idx = n * HDIM + 2 * i;
        float xr = buf[idx], xi = buf[idx + 1];
        *(__half2*)(dst + (size_t)row * DIMC + idx) =
            __floats2half2_rn((xr * c - xi * s) * sc,
                              (xr * s + xi * c) * sc);
    }
}

// ---------------------------------------------------------------------------
// Flash attention with STATIC-MAX softmax (no online max machinery):
// scores are log2-domain; P = exp2h(s - SMAX) with fixed SMAX=6
// (Cauchy-Schwarz bound: |s| <= sqrt(128)*log2e = 16.32, so P <= 2^10.32,
//  far below fp16 max; typical dominant arg ~ -1). oacc never rescaled;
// l accumulated per-thread own-half, combined once in the epilogue.
// Per tile: top sync, post-QK sync (K refill), one P-ordering barrier.
// 4(m) x 2(n) warps, BQ=128, BK=64, 256 threads, 2 CTAs/SM.
// ---------------------------------------------------------------------------
#define SMAXC 6.0f
#define AKSTR 136
#define AVSTR 72
#define APSTR 72
#define AQ_H 0
#define AK_H 17408
#define AV_H 26112
#define AP_H 44544
#define AEX_B (53760 * 2)
#define ATT_SMEM_BYTES 109568

__global__ void __launch_bounds__(256, 2) attn_mma()
{
    extern __shared__ __half smh[];
    const uint32_t base = (uint32_t)__cvta_generic_to_shared(smh);
    const uint32_t Qb = base;
    const uint32_t Kb = base + AK_H * 2;
    const uint32_t Vb = base + AV_H * 2;
    const uint32_t Pb = base + AP_H * 2;
    float* exS = (float*)((char*)smh + AEX_B);

    const int tid = threadIdx.x;
    const int lane = tid & 31;
    const int w = tid >> 5;
    const int wm = w & 3;
    const int wn = w >> 2;
    const int gid = lane >> 2;
    const int tig = lane & 3;
    const int qrow = wm * 32;
    const int q0 = blockIdx.x * 128;
    const int head = blockIdx.y;
    const int hoff = head * HDIM;

    const int aRow = lane & 15;
    const int aCol = (lane >> 4) * 8;
    const uint32_t qOff0 = ((qrow + aRow) * AKSTR + aCol) * 2;
    const uint32_t qOff1 = qOff0 + 16 * AKSTR * 2;
    const uint32_t pOff0 = ((qrow + aRow) * APSTR + aCol) * 2;
    const uint32_t pOff1 = pOff0 + 16 * APSTR * 2;
    const int bRow = (lane & 7) + ((lane >> 4) & 1) * 8;
    const int bCol = ((lane >> 3) & 1) * 8;
    const uint32_t kOff = ((wn * 32 + bRow) * AKSTR + bCol) * 2;
    const uint32_t vOff = ((wn * 64 + bRow) * AVSTR + bCol) * 2;

    // ---- initial fills: Q (persistent), K(0), V(0) ----
#pragma unroll
    for (int i = 0; i < 8; ++i) {
        int c = tid + i * 256;
        int r = c >> 4, c16 = c & 15;
        int sr = q0 + r; if (sr > SEQ - 1) sr = SEQ - 1;
        cp16(Qb + (r * AKSTR + 8 * c16) * 2,
             g_qh + (size_t)sr * DIMC + hoff + 8 * c16);
    }
    auto fillK = [&](int k0) {
#pragma unroll
        for (int i = 0; i < 4; ++i) {
            int c = tid + i * 256;
            int r = c >> 4, c16 = c & 15;
            int sr = k0 + r; if (sr > SEQ - 1) sr = SEQ - 1;
            cp16(Kb + (r * AKSTR + 8 * c16) * 2,
                 g_kh + (size_t)sr * DIMC + hoff + 8 * c16);
        }
    };
    auto fillV = [&](int buf, int k0) {
#pragma unroll
        for (int i = 0; i < 4; ++i) {
            int c = tid + i * 256;
            int r = c >> 3, c8 = c & 7;
            cp16(Vb + (buf * 128 * AVSTR + r * AVSTR + 8 * c8) * 2,
                 g_vt + (size_t)(hoff + r) * SEQ + k0 + 8 * c8);
        }
    };
    fillK(0);
    fillV(0, 0);
    cp_commit();

    float oacc[2][8][4];
#pragma unroll
    for (int mq = 0; mq < 2; ++mq)
#pragma unroll
        for (int dt = 0; dt < 8; ++dt)
#pragma unroll
            for (int i = 0; i < 4; ++i) oacc[mq][dt][i] = 0.f;
    float l[2][2] = {{0.f, 0.f}, {0.f, 0.f}};   // per-thread OWN-HALF partials

    const int nkt = (SEQ + 63) / 64;   // 85
    for (int kt = 0; kt < nkt; ++kt) {
        const int buf = kt & 1;
        const int k0 = kt * 64;
        cp_wait<0>();
        __syncthreads();      // orders ALL cross-tile hazards (K,V,P)

        // ---- V(t+1) prefetch ----
        if (kt + 1 < nkt) fillV(buf ^ 1, k0 + 64);

        // ---- S = Q K^T (scores in log2 domain; Q pre-scaled) ----
        float sacc[2][4][4];
#pragma unroll
        for (int mq = 0; mq < 2; ++mq)
#pragma unroll
            for (int nt = 0; nt < 4; ++nt)
#pragma unroll
                for (int i = 0; i < 4; ++i) sacc[mq][nt][i] = 0.f;

#pragma unroll
        for (int ks = 0; ks < 8; ++ks) {
            uint32_t qa0[4], qa1[4];
            ldsm4(qa0[0], qa0[1], qa0[2], qa0[3], Qb + qOff0 + ks * 32);
            ldsm4(qa1[0], qa1[1], qa1[2], qa1[3], Qb + qOff1 + ks * 32);
#pragma unroll
            for (int p = 0; p < 2; ++p) {
                uint32_t b0, b1, b2, b3;
                ldsm4(b0, b1, b2, b3, Kb + kOff + (p * 16 * AKSTR + ks * 16) * 2);
                mma_f16(sacc[0][2 * p],     qa0, b0, b1);
                mma_f16(sacc[0][2 * p + 1], qa0, b2, b3);
                mma_f16(sacc[1][2 * p],     qa1, b0, b1);
                mma_f16(sacc[1][2 * p + 1], qa1, b2, b3);
            }
        }

        __syncthreads();      // all warps done reading K -> safe to refill
        if (kt + 1 < nkt) fillK(k0 + 64);
        cp_commit();          // one group: V(t+1) + K(t+1)

        // ---- mask tail keys (warp's slice) ----
        const int krem = SEQ - k0 - wn * 32;
        if (krem < 32) {
#pragma unroll
            for (int mq = 0; mq < 2; ++mq)
#pragma unroll
                for (int nt = 0; nt < 4; ++nt) {
                    int c = nt * 8 + 2 * tig;
                    if (c >= krem)     { sacc[mq][nt][0] = -1e30f; sacc[mq][nt][2] = -1e30f; }
                    if (c + 1 >= krem) { sacc[mq][nt][1] = -1e30f; sacc[mq][nt][3] = -1e30f; }
                }
        }

        // ---- P = exp2(s - SMAX) fp16 pairs; own-half partial sums ----
        float2 ps2[2][2] = {{{0.f,0.f},{0.f,0.f}}, {{0.f,0.f},{0.f,0.f}}};
        uint32_t ph[2][2][4];
#pragma unroll
        for (int mq = 0; mq < 2; ++mq) {
#pragma unroll
            for (int nt = 0; nt < 4; ++nt) {
                int kc = nt >> 1, o = (nt & 1) * 2;
                ph[mq][kc][o] = pexp2(sacc[mq][nt][0] - SMAXC,
                                      sacc[mq][nt][1] - SMAXC, ps2[mq][0]);
                ph[mq][kc][o + 1] = pexp2(sacc[mq][nt][2] - SMAXC,
                                          sacc[mq][nt][3] - SMAXC, ps2[mq][1]);
            }
#pragma unroll
            for (int kc = 0; kc < 2; ++kc) {
                uint32_t pr = Pb + ((qrow + mq * 16 + gid) * APSTR
                                    + wn * 32 + kc * 16 + 2 * tig) * 2;
                sts32(pr,                      ph[mq][kc][0]);
                sts32(pr + 8 * APSTR * 2,      ph[mq][kc][1]);
                sts32(pr + 16,                 ph[mq][kc][2]);
                sts32(pr + 8 * APSTR * 2 + 16, ph[mq][kc][3]);
            }
        }
#pragma unroll
        for (int mq = 0; mq < 2; ++mq)
#pragma unroll
            for (int h = 0; h < 2; ++h)
                l[mq][h] += ps2[mq][h].x + ps2[mq][h].y;

        // ---- bare pair barrier: P stores visible before cross-half reads ----
        barn(1 + wm, 64);

        // ---- O += P V (32 rows x 64 d per warp, all 64 keys) ----
        const uint32_t vbA = Vb + buf * 128 * AVSTR * 2 + vOff;
#pragma unroll
        for (int kc = 0; kc < 4; ++kc) {
            uint32_t pa0[4], pa1[4];
            if ((kc >> 1) == wn) {
#pragma unroll
                for (int i = 0; i < 4; ++i) {
                    pa0[i] = ph[0][kc & 1][i];
                    pa1[i] = ph[1][kc & 1][i];
                }
            } else {
                ldsm4(pa0[0], pa0[1], pa0[2], pa0[3], Pb + pOff0 + kc * 32);
                ldsm4(pa1[0], pa1[1], pa1[2], pa1[3], Pb + pOff1 + kc * 32);
            }
#pragma unroll
            for (int p = 0; p < 4; ++p) {
                uint32_t v0, v1, v2, v3;
                ldsm4(v0, v1, v2, v3, vbA + (p * 16 * AVSTR + kc * 16) * 2);
                mma_f16(oacc[0][2 * p],     pa0, v0, v1);
                mma_f16(oacc[0][2 * p + 1], pa0, v2, v3);
                mma_f16(oacc[1][2 * p],     pa1, v0, v1);
                mma_f16(oacc[1][2 * p + 1], pa1, v2, v3);
            }
        }
        // no bottom sync: top-of-tile __syncthreads orders all reuse
    }

    // ---- epilogue: combine l across quad, then across key-half warps ----
#pragma unroll
    for (int mq = 0; mq < 2; ++mq)
#pragma unroll
        for (int h = 0; h < 2; ++h) {
            l[mq][h] += __shfl_xor_sync(0xffffffffu, l[mq][h], 1);
            l[mq][h] += __shfl_xor_sync(0xffffffffu, l[mq][h], 2);
        }
    if (tig == 0) {
#pragma unroll
        for (int mq = 0; mq < 2; ++mq) {
            exS[wn * 128 + qrow + mq * 16 + gid]     = l[mq][0];
            exS[wn * 128 + qrow + mq * 16 + gid + 8] = l[mq][1];
        }
    }
    barn(1 + wm, 64);

#pragma unroll
    for (int mq = 0; mq < 2; ++mq) {
        float lt0 = l[mq][0] + exS[(wn ^ 1) * 128 + qrow + mq * 16 + gid];
        float lt1 = l[mq][1] + exS[(wn ^ 1) * 128 + qrow + mq * 16 + gid + 8];
        float inv0 = 1.f / lt0, inv1 = 1.f / lt1;
        int r0 = q0 + qrow + mq * 16 + gid;
        int r1 = r0 + 8;
#pragma unroll
        for (int dt = 0; dt < 8; ++dt) {
            int col = hoff + wn * 64 + dt * 8 + 2 * tig;
            if (r0 < SEQ)
                *(__half2*)(g_ao + (size_t)r0 * DIMC + col) =
                    __floats2half2_rn(oacc[mq][dt][0] * inv0, oacc[mq][dt][1] * inv0);
            if (r1 < SEQ)
                *(__half2*)(g_ao + (size_t)r1 * DIMC + col) =
                    __floats2half2_rn(oacc[mq][dt][2] * inv1, oacc[mq][dt][3] * inv1);
        }
    }
}

// ---------------------------------------------------------------------------
extern "C" void kernel_launch(void* const* d_in, const int* in_sizes, int n_in,
                              void* d_out, int out_size)
{
    const float* x    = (const float*)d_in[0];
    const float* q_b  = (const float*)d_in[2];
    const float* k_b  = (const float*)d_in[4];
    const float* v_b  = (const float*)d_in[6];
    const float* o_b  = (const float*)d_in[8];
    const float* nqw  = (const float*)d_in[9];
    const float* nkw  = (const float*)d_in[10];
    const float* cosT = (const float*)d_in[11];
    const float* sinT = (const float*)d_in[12];
    float* out = (float*)d_out;

    float *dqf, *dkf;
    __half *dvt, *dxh, *dwh, *dao;
    cudaGetSymbolAddress((void**)&dqf, g_qf);
    cudaGetSymbolAddress((void**)&dkf, g_kf);
    cudaGetSymbolAddress((void**)&dvt, g_vt);
    cudaGetSymbolAddress((void**)&dxh, g_xh);
    cudaGetSymbolAddress((void**)&dwh, g_wh);
    cudaGetSymbolAddress((void**)&dao, g_ao);

    // convert inputs to fp16
    const int nx4 = SEQ * DIMC / 4;
    const int nw4 = DIMC * DIMC / 4;
    conv_h<<<(nx4 + 255) / 256, 256>>>((const float4*)x, (__half2*)dxh, nx4);
    conv_h4<<<dim3((nw4 + 255) / 256, 4), 256>>>(
        (const float4*)d_in[1], (const float4*)d_in[3],
        (const float4*)d_in[5], (const float4*)d_in[7],
        (__half2*)dwh, nw4);

    cudaFuncSetAttribute(gemm_qkv,
                         cudaFuncAttributeMaxDynamicSharedMemorySize, GSM_BYTES);
    cudaFuncSetAttribute(gemm_o,
                         cudaFuncAttributeMaxDynamicSharedMemorySize, GSM_BYTES);

    dim3 gQKV(DIMC / 128, (SEQ + 127) / 128, 3);
    gemm_qkv<<<gQKV, 256, GSM_BYTES>>>(dxh, dwh, q_b, k_b, v_b,
                                       dqf, dkf, dvt, SEQ);

    norm_rope_kernel<<<dim3(SEQ, 2), 256>>>(nqw, nkw, cosT, sinT);

    cudaFuncSetAttribute(attn_mma,
                         cudaFuncAttributeMaxDynamicSharedMemorySize, ATT_SMEM_BYTES);
    attn_mma<<<dim3((SEQ + 127) / 128, NHEAD), 256, ATT_SMEM_BYTES>>>();

    dim3 gGemm(DIMC / 128, (SEQ + 127) / 128);
    gemm_o<<<gGemm, 256, GSM_BYTES>>>(dao, dwh + 3 * (size_t)DIMC * DIMC,
                                      o_b, out, SEQ);
}

// round 17
// speedup vs baseline: 1.1581x; 1.0090x over previous
#include <cuda_runtime.h>
#include <cuda_fp16.h>
#include <math.h>
#include <stdint.h>

#define DIMC 1536
#define NHEAD 12
#define HDIM 128
#define SEQ 5400
#define GHW 900
#define GWID 30

// scratch (device globals: no allocations allowed)
__device__ float  g_qf[SEQ * DIMC];
__device__ float  g_kf[SEQ * DIMC];
__device__ __half g_qh[SEQ * DIMC];
__device__ __half g_kh[SEQ * DIMC];
__device__ __half g_vt[NHEAD * HDIM * SEQ + 256];   // [head][d][seq] (+pad)
__device__ __half g_ao[SEQ * DIMC];
__device__ __half g_xh[SEQ * DIMC];
__device__ __half g_wh[4][DIMC * DIMC];

// ---------------------------------------------------------------------------
// helpers
// ---------------------------------------------------------------------------
__device__ __forceinline__ void mma_f16(float* c, const uint32_t* a,
                                        uint32_t b0, uint32_t b1) {
    asm volatile(
        "mma.sync.aligned.m16n8k16.row.col.f32.f16.f16.f32 "
        "{%0,%1,%2,%3}, {%4,%5,%6,%7}, {%8,%9}, {%0,%1,%2,%3};\n"
        : "+f"(c[0]), "+f"(c[1]), "+f"(c[2]), "+f"(c[3])
        : "r"(a[0]), "r"(a[1]), "r"(a[2]), "r"(a[3]), "r"(b0), "r"(b1));
}

__device__ __forceinline__ void ldsm4(uint32_t& r0, uint32_t& r1,
                                      uint32_t& r2, uint32_t& r3, uint32_t a) {
    asm volatile("ldmatrix.sync.aligned.m8n8.x4.shared.b16 {%0,%1,%2,%3}, [%4];"
                 : "=r"(r0), "=r"(r1), "=r"(r2), "=r"(r3) : "r"(a) : "memory");
}

__device__ __forceinline__ void sts32(uint32_t a, uint32_t v) {
    asm volatile("st.shared.b32 [%0], %1;" :: "r"(a), "r"(v) : "memory");
}

__device__ __forceinline__ void barn(int id, int cnt) {
    asm volatile("bar.sync %0, %1;" :: "r"(id), "r"(cnt) : "memory");
}

__device__ __forceinline__ void cp16(uint32_t dst, const void* src) {
    asm volatile("cp.async.cg.shared.global [%0], [%1], 16;\n"
                 :: "r"(dst), "l"(src));
}
__device__ __forceinline__ void cp_commit() {
    asm volatile("cp.async.commit_group;\n");
}
template <int N> __device__ __forceinline__ void cp_wait() {
    asm volatile("cp.async.wait_group %0;\n" :: "n"(N));
}

// exp2 on a packed pair: arg pair (fp32) -> fp16x2 -> h2exp2 -> packed P
__device__ __forceinline__ uint32_t pexp2(float a, float b, float2& fsum) {
    __half2 h = h2exp2(__floats2half2_rn(a, b));
    float2 f = __half22float2(h);
    fsum.x += f.x; fsum.y += f.y;
    return *(uint32_t*)&h;
}

// ---------------------------------------------------------------------------
// fp32 -> fp16 conversion copies
// ---------------------------------------------------------------------------
__global__ void __launch_bounds__(256) conv_h(
    const float4* __restrict__ s, __half2* __restrict__ d, int n4)
{
    int i = blockIdx.x * 256 + threadIdx.x;
    if (i < n4) {
        float4 v = s[i];
        d[2 * i + 0] = __floats2half2_rn(v.x, v.y);
        d[2 * i + 1] = __floats2half2_rn(v.z, v.w);
    }
}

__global__ void __launch_bounds__(256) conv_h4(
    const float4* __restrict__ s0, const float4* __restrict__ s1,
    const float4* __restrict__ s2, const float4* __restrict__ s3,
    __half2* __restrict__ d, int n4)
{
    const float4* s = (blockIdx.y == 0) ? s0 : (blockIdx.y == 1) ? s1
                     : (blockIdx.y == 2) ? s2 : s3;
    __half2* dd = d + (size_t)blockIdx.y * n4 * 2;
    int i = blockIdx.x * 256 + threadIdx.x;
    if (i < n4) {
        float4 v = s[i];
        dd[2 * i + 0] = __floats2half2_rn(v.x, v.y);
        dd[2 * i + 1] = __floats2half2_rn(v.z, v.w);
    }
}

// ---------------------------------------------------------------------------
// FP16 GEMM core: 128x128 tile, BK=64, 2-stage cp.async pipeline (24 k-blocks),
// ldmatrix fragments, warp tile 64x32 (8 warps 2x4).  [round-12 winner]
// ---------------------------------------------------------------------------
#define GSTRH 72                       // halves per smem row (64 + 8 pad)
#define GBUF_H (128 * GSTRH)           // halves per stage per matrix
#define GSM_BYTES (2 * GBUF_H * 2 * 2) // 73728 bytes

struct GemmCore {
    template <typename EPI>
    static __device__ __forceinline__ void run(
        const __half* __restrict__ A, const __half* __restrict__ B,
        int bm, int bn, int M, __half* gsm, EPI epi)
    {
        __half* sA = gsm;
        __half* sB = gsm + 2 * GBUF_H;
        const int tid = threadIdx.x;
        const int lane = tid & 31;
        const int wid = tid >> 5;
        const int wm = wid & 1;
        const int wn = wid >> 1;
        const uint32_t aAddr = (uint32_t)__cvta_generic_to_shared(sA);
        const uint32_t bAddr = (uint32_t)__cvta_generic_to_shared(sB);
        const uint32_t aOff = ((wm * 64 + (lane & 15)) * GSTRH + (lane >> 4) * 8) * 2;
        const uint32_t bOff = ((wn * 32 + (lane & 7) + ((lane >> 4) & 1) * 8) * GSTRH
                               + ((lane >> 3) & 1) * 8) * 2;

        float acc[4][4][4];
#pragma unroll
        for (int mt = 0; mt < 4; ++mt)
#pragma unroll
            for (int nt = 0; nt < 4; ++nt)
#pragma unroll
                for (int i = 0; i < 4; ++i) acc[mt][nt][i] = 0.f;

        auto fill = [&](int stg, int kb) {
            const int k0 = kb * 64;
            const uint32_t ab = aAddr + stg * GBUF_H * 2;
            const uint32_t bb = bAddr + stg * GBUF_H * 2;
#pragma unroll
            for (int i = 0; i < 4; ++i) {
                int c = tid + i * 256;          // 0..1023
                int r = c >> 3, c8 = c & 7;
                int ra = bm + r; if (ra > M - 1) ra = M - 1;
                cp16(ab + (r * GSTRH + 8 * c8) * 2,
                     A + (size_t)ra * DIMC + k0 + 8 * c8);
                cp16(bb + (r * GSTRH + 8 * c8) * 2,
                     B + (size_t)(bn + r) * DIMC + k0 + 8 * c8);
            }
            cp_commit();
        };

        fill(0, 0);

        const int NKB = DIMC / 64;   // 24
        for (int kb = 0; kb < NKB; ++kb) {
            const int buf = kb & 1;
            if (kb + 1 < NKB) {
                fill(buf ^ 1, kb + 1);
                cp_wait<1>();
            } else {
                cp_wait<0>();
            }
            __syncthreads();

            const uint32_t ab = aAddr + buf * GBUF_H * 2 + aOff;
            const uint32_t bb = bAddr + buf * GBUF_H * 2 + bOff;
#pragma unroll
            for (int ks = 0; ks < 4; ++ks) {
                uint32_t af[4][4], bf[2][4];
#pragma unroll
                for (int mt = 0; mt < 4; ++mt)
                    ldsm4(af[mt][0], af[mt][1], af[mt][2], af[mt][3],
                          ab + (mt * 16 * GSTRH + ks * 16) * 2);
#pragma unroll
                for (int p = 0; p < 2; ++p)
                    ldsm4(bf[p][0], bf[p][1], bf[p][2], bf[p][3],
                          bb + (p * 16 * GSTRH + ks * 16) * 2);
#pragma unroll
                for (int mt = 0; mt < 4; ++mt)
#pragma unroll
                    for (int p = 0; p < 2; ++p) {
                        mma_f16(acc[mt][2 * p],     af[mt], bf[p][0], bf[p][1]);
                        mma_f16(acc[mt][2 * p + 1], af[mt], bf[p][2], bf[p][3]);
                    }
            }
            __syncthreads();
        }
        epi(acc);
    }
};

__global__ void __launch_bounds__(256, 2) gemm_qkv(
    const __half* __restrict__ A, const __half* __restrict__ W,
    const float* __restrict__ qb, const float* __restrict__ kb_,
    const float* __restrict__ vb,
    float* __restrict__ Cq, float* __restrict__ Ck,
    __half* __restrict__ Vt, int M)
{
    extern __shared__ __half gsm[];
    const int z = blockIdx.z;
    const int tid = threadIdx.x;
    const int lane = tid & 31;
    const int wid = tid >> 5;
    const int gid = lane >> 2;
    const int tig = lane & 3;
    const int wm = wid & 1;
    const int wn = wid >> 1;
    const int bm = blockIdx.y * 128;
    const int bn = blockIdx.x * 128;
    const __half* B = W + (size_t)z * DIMC * DIMC;
    const float* bias = (z == 0) ? qb : (z == 1) ? kb_ : vb;
    float* Cf = (z == 0) ? Cq : Ck;

    GemmCore::run(A, B, bm, bn, M, gsm, [&](float acc[4][4][4]) {
#pragma unroll
        for (int mt = 0; mt < 4; ++mt) {
            int r0 = bm + wm * 64 + mt * 16 + gid;
            int r1 = r0 + 8;
#pragma unroll
            for (int nt = 0; nt < 4; ++nt) {
                int col = bn + wn * 32 + nt * 8 + 2 * tig;
                float b0 = __ldg(bias + col), b1 = __ldg(bias + col + 1);
                if (z < 2) {
                    if (r0 < M)
                        *(float2*)(Cf + (size_t)r0 * DIMC + col) =
                            make_float2(acc[mt][nt][0] + b0, acc[mt][nt][1] + b1);
                    if (r1 < M)
                        *(float2*)(Cf + (size_t)r1 * DIMC + col) =
                            make_float2(acc[mt][nt][2] + b0, acc[mt][nt][3] + b1);
                } else {
                    if (r0 < M) {
                        Vt[(size_t)col * SEQ + r0]       = __float2half_rn(acc[mt][nt][0] + b0);
                        Vt[(size_t)(col + 1) * SEQ + r0] = __float2half_rn(acc[mt][nt][1] + b1);
                    }
                    if (r1 < M) {
                        Vt[(size_t)col * SEQ + r1]       = __float2half_rn(acc[mt][nt][2] + b0);
                        Vt[(size_t)(col + 1) * SEQ + r1] = __float2half_rn(acc[mt][nt][3] + b1);
                    }
                }
            }
        }
    });
}

__global__ void __launch_bounds__(256, 2) gemm_o(
    const __half* __restrict__ A, const __half* __restrict__ B,
    const float* __restrict__ bias, float* __restrict__ Cf, int M)
{
    extern __shared__ __half gsm[];
    const int tid = threadIdx.x;
    const int lane = tid & 31;
    const int wid = tid >> 5;
    const int gid = lane >> 2;
    const int tig = lane & 3;
    const int wm = wid & 1;
    const int wn = wid >> 1;
    const int bm = blockIdx.y * 128;
    const int bn = blockIdx.x * 128;

    GemmCore::run(A, B, bm, bn, M, gsm, [&](float acc[4][4][4]) {
#pragma unroll
        for (int mt = 0; mt < 4; ++mt) {
            int r0 = bm + wm * 64 + mt * 16 + gid;
            int r1 = r0 + 8;
#pragma unroll
            for (int nt = 0; nt < 4; ++nt) {
                int col = bn + wn * 32 + nt * 8 + 2 * tig;
                float b0 = __ldg(bias + col), b1 = __ldg(bias + col + 1);
                if (r0 < M)
                    *(float2*)(Cf + (size_t)r0 * DIMC + col) =
                        make_float2(acc[mt][nt][0] + b0, acc[mt][nt][1] + b1);
                if (r1 < M)
                    *(float2*)(Cf + (size_t)r1 * DIMC + col) =
                        make_float2(acc[mt][nt][2] + b0, acc[mt][nt][3] + b1);
            }
        }
    });
}

// ---------------------------------------------------------------------------
// Fused RMSNorm + RoPE: reads fp32 q/k projections, writes fp16.
// q pre-scaled by log2(e)/sqrt(HD)  (QK scores come out in log2 domain).
// ---------------------------------------------------------------------------
__global__ void __launch_bounds__(256) norm_rope_kernel(
    const float* __restrict__ nqw, const float* __restrict__ nkw,
    const float* __restrict__ cosT, const float* __restrict__ sinT)
{
    __shared__ float buf[DIMC];
    __shared__ float red[8];
    const int row = blockIdx.x;
    const float* src = blockIdx.y ? g_kf : g_qf;
    __half* dst = blockIdx.y ? g_kh : g_qh;
    const float* w = blockIdx.y ? nkw : nqw;
    const float sc = blockIdx.y ? 1.0f
                   : (0.08838834764831845f * 1.4426950408889634f);
    const int tid = threadIdx.x;

    float ss = 0.f;
#pragma unroll
    for (int j = tid; j < DIMC; j += 256) {
        float v = src[(size_t)row * DIMC + j];
        buf[j] = v;
        ss += v * v;
    }
#pragma unroll
    for (int o = 16; o; o >>= 1) ss += __shfl_xor_sync(0xffffffffu, ss, o);
    if ((tid & 31) == 0) red[tid >> 5] = ss;
    __syncthreads();
    float tot = 0.f;
#pragma unroll
    for (int i = 0; i < 8; ++i) tot += red[i];
    const float rms = rsqrtf(tot * (1.0f / DIMC) + 1e-6f);
#pragma unroll
    for (int j = tid; j < DIMC; j += 256) buf[j] = buf[j] * rms * w[j];
    __syncthreads();

    const int f = row / GHW;
    const int rem = row - f * GHW;
    const int h = rem / GWID;
    const int ww = rem - h * GWID;
#pragma unroll
    for (int p = tid; p < DIMC / 2; p += 256) {
        int n = p >> 6;
        int i = p & 63;
        int pos = (i < 22) ? f : (i < 43) ? h : ww;
        float c = cosT[pos * 64 + i];
        float s = sinT[pos * 64 + i];
        int idx = n * HDIM + 2 * i;
        float xr = buf[idx], xi = buf[idx + 1];
        *(__half2*)(dst + (size_t)row * DIMC + idx) =
            __floats2half2_rn((xr * c - xi * s) * sc,
                              (xr * s + xi * c) * sc);
    }
}

// ---------------------------------------------------------------------------
// Flash attention, static-max softmax, TWO barriers per tile:
//   top __syncthreads  : K(t)/V(t) ready + P region reuse safe
//   mid __syncthreads  : (a) all QK reads of K done -> K refill safe
//                        (b) P stores visible -> cross-half P reads safe
// K refill moved after the P phase (window = PV, absorbed by top cp_wait).
// 4(m) x 2(n) warps, BQ=128, BK=64, 256 threads, 2 CTAs/SM.
// ---------------------------------------------------------------------------
#define SMAXC 6.0f
#define AKSTR 136
#define AVSTR 72
#define APSTR 72
#define AQ_H 0
#define AK_H 17408
#define AV_H 26112
#define AP_H 44544
#define AEX_B (53760 * 2)
#define ATT_SMEM_BYTES 109568

__global__ void __launch_bounds__(256, 2) attn_mma()
{
    extern __shared__ __half smh[];
    const uint32_t base = (uint32_t)__cvta_generic_to_shared(smh);
    const uint32_t Qb = base;
    const uint32_t Kb = base + AK_H * 2;
    const uint32_t Vb = base + AV_H * 2;
    const uint32_t Pb = base + AP_H * 2;
    float* exS = (float*)((char*)smh + AEX_B);

    const int tid = threadIdx.x;
    const int lane = tid & 31;
    const int w = tid >> 5;
    const int wm = w & 3;
    const int wn = w >> 2;
    const int gid = lane >> 2;
    const int tig = lane & 3;
    const int qrow = wm * 32;
    const int q0 = blockIdx.x * 128;
    const int head = blockIdx.y;
    const int hoff = head * HDIM;

    const int aRow = lane & 15;
    const int aCol = (lane >> 4) * 8;
    const uint32_t qOff0 = ((qrow + aRow) * AKSTR + aCol) * 2;
    const uint32_t qOff1 = qOff0 + 16 * AKSTR * 2;
    const uint32_t pOff0 = ((qrow + aRow) * APSTR + aCol) * 2;
    const uint32_t pOff1 = pOff0 + 16 * APSTR * 2;
    const int bRow = (lane & 7) + ((lane >> 4) & 1) * 8;
    const int bCol = ((lane >> 3) & 1) * 8;
    const uint32_t kOff = ((wn * 32 + bRow) * AKSTR + bCol) * 2;
    const uint32_t vOff = ((wn * 64 + bRow) * AVSTR + bCol) * 2;

    // ---- initial fills: Q (persistent), K(0), V(0) ----
#pragma unroll
    for (int i = 0; i < 8; ++i) {
        int c = tid + i * 256;
        int r = c >> 4, c16 = c & 15;
        int sr = q0 + r; if (sr > SEQ - 1) sr = SEQ - 1;
        cp16(Qb + (r * AKSTR + 8 * c16) * 2,
             g_qh + (size_t)sr * DIMC + hoff + 8 * c16);
    }
    auto fillK = [&](int k0) {
#pragma unroll
        for (int i = 0; i < 4; ++i) {
            int c = tid + i * 256;
            int r = c >> 4, c16 = c & 15;
            int sr = k0 + r; if (sr > SEQ - 1) sr = SEQ - 1;
            cp16(Kb + (r * AKSTR + 8 * c16) * 2,
                 g_kh + (size_t)sr * DIMC + hoff + 8 * c16);
        }
    };
    auto fillV = [&](int buf, int k0) {
#pragma unroll
        for (int i = 0; i < 4; ++i) {
            int c = tid + i * 256;
            int r = c >> 3, c8 = c & 7;
            cp16(Vb + (buf * 128 * AVSTR + r * AVSTR + 8 * c8) * 2,
                 g_vt + (size_t)(hoff + r) * SEQ + k0 + 8 * c8);
        }
    };
    fillK(0);
    fillV(0, 0);
    cp_commit();

    float oacc[2][8][4];
#pragma unroll
    for (int mq = 0; mq < 2; ++mq)
#pragma unroll
        for (int dt = 0; dt < 8; ++dt)
#pragma unroll
            for (int i = 0; i < 4; ++i) oacc[mq][dt][i] = 0.f;
    float l[2][2] = {{0.f, 0.f}, {0.f, 0.f}};   // per-thread OWN-HALF partials

    const int nkt = (SEQ + 63) / 64;   // 85
    for (int kt = 0; kt < nkt; ++kt) {
        const int buf = kt & 1;
        const int k0 = kt * 64;
        cp_wait<0>();
        __syncthreads();      // K(t)/V(t) ready; P region reuse safe

        // ---- V(t+1) prefetch (issued now, committed mid-tile) ----
        if (kt + 1 < nkt) fillV(buf ^ 1, k0 + 64);

        // ---- S = Q K^T (scores in log2 domain; Q pre-scaled) ----
        float sacc[2][4][4];
#pragma unroll
        for (int mq = 0; mq < 2; ++mq)
#pragma unroll
            for (int nt = 0; nt < 4; ++nt)
#pragma unroll
                for (int i = 0; i < 4; ++i) sacc[mq][nt][i] = 0.f;

#pragma unroll
        for (int ks = 0; ks < 8; ++ks) {
            uint32_t qa0[4], qa1[4];
            ldsm4(qa0[0], qa0[1], qa0[2], qa0[3], Qb + qOff0 + ks * 32);
            ldsm4(qa1[0], qa1[1], qa1[2], qa1[3], Qb + qOff1 + ks * 32);
#pragma unroll
            for (int p = 0; p < 2; ++p) {
                uint32_t b0, b1, b2, b3;
                ldsm4(b0, b1, b2, b3, Kb + kOff + (p * 16 * AKSTR + ks * 16) * 2);
                mma_f16(sacc[0][2 * p],     qa0, b0, b1);
                mma_f16(sacc[0][2 * p + 1], qa0, b2, b3);
                mma_f16(sacc[1][2 * p],     qa1, b0, b1);
                mma_f16(sacc[1][2 * p + 1], qa1, b2, b3);
            }
        }

        // ---- mask tail keys (warp's slice) ----
        const int krem = SEQ - k0 - wn * 32;
        if (krem < 32) {
#pragma unroll
            for (int mq = 0; mq < 2; ++mq)
#pragma unroll
                for (int nt = 0; nt < 4; ++nt) {
                    int c = nt * 8 + 2 * tig;
                    if (c >= krem)     { sacc[mq][nt][0] = -1e30f; sacc[mq][nt][2] = -1e30f; }
                    if (c + 1 >= krem) { sacc[mq][nt][1] = -1e30f; sacc[mq][nt][3] = -1e30f; }
                }
        }

        // ---- P = exp2(s - SMAX) fp16 pairs; own-half partial sums ----
        float2 ps2[2][2] = {{{0.f,0.f},{0.f,0.f}}, {{0.f,0.f},{0.f,0.f}}};
        uint32_t ph[2][2][4];
#pragma unroll
        for (int mq = 0; mq < 2; ++mq) {
#pragma unroll
            for (int nt = 0; nt < 4; ++nt) {
                int kc = nt >> 1, o = (nt & 1) * 2;
                ph[mq][kc][o] = pexp2(sacc[mq][nt][0] - SMAXC,
                                      sacc[mq][nt][1] - SMAXC, ps2[mq][0]);
                ph[mq][kc][o + 1] = pexp2(sacc[mq][nt][2] - SMAXC,
                                          sacc[mq][nt][3] - SMAXC, ps2[mq][1]);
            }
#pragma unroll
            for (int kc = 0; kc < 2; ++kc) {
                uint32_t pr = Pb + ((qrow + mq * 16 + gid) * APSTR
                                    + wn * 32 + kc * 16 + 2 * tig) * 2;
                sts32(pr,                      ph[mq][kc][0]);
                sts32(pr + 8 * APSTR * 2,      ph[mq][kc][1]);
                sts32(pr + 16,                 ph[mq][kc][2]);
                sts32(pr + 8 * APSTR * 2 + 16, ph[mq][kc][3]);
            }
        }
#pragma unroll
        for (int mq = 0; mq < 2; ++mq)
#pragma unroll
            for (int h = 0; h < 2; ++h)
                l[mq][h] += ps2[mq][h].x + ps2[mq][h].y;

        // ---- single mid-tile barrier: QK reads done AND P stores visible ----
        __syncthreads();
        if (kt + 1 < nkt) fillK(k0 + 64);
        cp_commit();          // group: V(t+1) + K(t+1)

        // ---- O += P V (32 rows x 64 d per warp, all 64 keys) ----
        const uint32_t vbA = Vb + buf * 128 * AVSTR * 2 + vOff;
#pragma unroll
        for (int kc = 0; kc < 4; ++kc) {
            uint32_t pa0[4], pa1[4];
            if ((kc >> 1) == wn) {
#pragma unroll
                for (int i = 0; i < 4; ++i) {
                    pa0[i] = ph[0][kc & 1][i];
                    pa1[i] = ph[1][kc & 1][i];
                }
            } else {
                ldsm4(pa0[0], pa0[1], pa0[2], pa0[3], Pb + pOff0 + kc * 32);
                ldsm4(pa1[0], pa1[1], pa1[2], pa1[3], Pb + pOff1 + kc * 32);
            }
#pragma unroll
            for (int p = 0; p < 4; ++p) {
                uint32_t v0, v1, v2, v3;
                ldsm4(v0, v1, v2, v3, vbA + (p * 16 * AVSTR + kc * 16) * 2);
                mma_f16(oacc[0][2 * p],     pa0, v0, v1);
                mma_f16(oacc[0][2 * p + 1], pa0, v2, v3);
                mma_f16(oacc[1][2 * p],     pa1, v0, v1);
                mma_f16(oacc[1][2 * p + 1], pa1, v2, v3);
            }
        }
        // no bottom sync: next tile's top __syncthreads orders all reuse
    }

    // ---- epilogue: combine l across quad, then across key-half warps ----
#pragma unroll
    for (int mq = 0; mq < 2; ++mq)
#pragma unroll
        for (int h = 0; h < 2; ++h) {
            l[mq][h] += __shfl_xor_sync(0xffffffffu, l[mq][h], 1);
            l[mq][h] += __shfl_xor_sync(0xffffffffu, l[mq][h], 2);
        }
    if (tig == 0) {
#pragma unroll
        for (int mq = 0; mq < 2; ++mq) {
            exS[wn * 128 + qrow + mq * 16 + gid]     = l[mq][0];
            exS[wn * 128 + qrow + mq * 16 + gid + 8] = l[mq][1];
        }
    }
    barn(1 + wm, 64);

#pragma unroll
    for (int mq = 0; mq < 2; ++mq) {
        float lt0 = l[mq][0] + exS[(wn ^ 1) * 128 + qrow + mq * 16 + gid];
        float lt1 = l[mq][1] + exS[(wn ^ 1) * 128 + qrow + mq * 16 + gid + 8];
        float inv0 = 1.f / lt0, inv1 = 1.f / lt1;
        int r0 = q0 + qrow + mq * 16 + gid;
        int r1 = r0 + 8;
#pragma unroll
        for (int dt = 0; dt < 8; ++dt) {
            int col = hoff + wn * 64 + dt * 8 + 2 * tig;
            if (r0 < SEQ)
                *(__half2*)(g_ao + (size_t)r0 * DIMC + col) =
                    __floats2half2_rn(oacc[mq][dt][0] * inv0, oacc[mq][dt][1] * inv0);
            if (r1 < SEQ)
                *(__half2*)(g_ao + (size_t)r1 * DIMC + col) =
                    __floats2half2_rn(oacc[mq][dt][2] * inv1, oacc[mq][dt][3] * inv1);
        }
    }
}

// ---------------------------------------------------------------------------
extern "C" void kernel_launch(void* const* d_in, const int* in_sizes, int n_in,
                              void* d_out, int out_size)
{
    const float* x    = (const float*)d_in[0];
    const float* q_b  = (const float*)d_in[2];
    const float* k_b  = (const float*)d_in[4];
    const float* v_b  = (const float*)d_in[6];
    const float* o_b  = (const float*)d_in[8];
    const float* nqw  = (const float*)d_in[9];
    const float* nkw  = (const float*)d_in[10];
    const float* cosT = (const float*)d_in[11];
    const float* sinT = (const float*)d_in[12];
    float* out = (float*)d_out;

    float *dqf, *dkf;
    __half *dvt, *dxh, *dwh, *dao;
    cudaGetSymbolAddress((void**)&dqf, g_qf);
    cudaGetSymbolAddress((void**)&dkf, g_kf);
    cudaGetSymbolAddress((void**)&dvt, g_vt);
    cudaGetSymbolAddress((void**)&dxh, g_xh);
    cudaGetSymbolAddress((void**)&dwh, g_wh);
    cudaGetSymbolAddress((void**)&dao, g_ao);

    // convert inputs to fp16
    const int nx4 = SEQ * DIMC / 4;
    const int nw4 = DIMC * DIMC / 4;
    conv_h<<<(nx4 + 255) / 256, 256>>>((const float4*)x, (__half2*)dxh, nx4);
    conv_h4<<<dim3((nw4 + 255) / 256, 4), 256>>>(
        (const float4*)d_in[1], (const float4*)d_in[3],
        (const float4*)d_in[5], (const float4*)d_in[7],
        (__half2*)dwh, nw4);

    cudaFuncSetAttribute(gemm_qkv,
                         cudaFuncAttributeMaxDynamicSharedMemorySize, GSM_BYTES);
    cudaFuncSetAttribute(gemm_o,
                         cudaFuncAttributeMaxDynamicSharedMemorySize, GSM_BYTES);

    dim3 gQKV(DIMC / 128, (SEQ + 127) / 128, 3);
    gemm_qkv<<<gQKV, 256, GSM_BYTES>>>(dxh, dwh, q_b, k_b, v_b,
                                       dqf, dkf, dvt, SEQ);

    norm_rope_kernel<<<dim3(SEQ, 2), 256>>>(nqw, nkw, cosT, sinT);

    cudaFuncSetAttribute(attn_mma,
                         cudaFuncAttributeMaxDynamicSharedMemorySize, ATT_SMEM_BYTES);
    attn_mma<<<dim3((SEQ + 127) / 128, NHEAD), 256, ATT_SMEM_BYTES>>>();

    dim3 gGemm(DIMC / 128, (SEQ + 127) / 128);
    gemm_o<<<gGemm, 256, GSM_BYTES>>>(dao, dwh + 3 * (size_t)DIMC * DIMC,
                                      o_b, out, SEQ);
}